// round 5
// baseline (speedup 1.0000x reference)
#include <cuda_runtime.h>
#include <math.h>
#include <stdint.h>

// Problem constants
#define CB   4
#define CL   512
#define CD   1024
#define CND  512
#define CED  64
#define CH   16
#define CMLP 2048
#define CDH  64
#define NTOK (CB*CL)        // 2048
#define MODW (6*CD)         // 6144
#define EPSF 1e-5f

// ---------------- scratch ----------------
__device__ float g_sln[NTOK*CND];
__device__ float g_t1[NTOK*CND];
__device__ float g_mod[NTOK*MODW];
__device__ float g_scores[(size_t)CB*CH*CL*CL];
__device__ float g_x[NTOK*CD];
__device__ float g_qkv[NTOK*3*CD];
__device__ float g_o[NTOK*CD];
__device__ float g_h2[NTOK*CD];
__device__ float g_t2[NTOK*CMLP];

// ---------------- utils ----------------
__device__ __forceinline__ float warp_sum(float v) {
#pragma unroll
    for (int o = 16; o > 0; o >>= 1) v += __shfl_xor_sync(0xffffffffu, v, o);
    return v;
}
__device__ __forceinline__ float warp_max(float v) {
#pragma unroll
    for (int o = 16; o > 0; o >>= 1) v = fmaxf(v, __shfl_xor_sync(0xffffffffu, v, o));
    return v;
}
__device__ __forceinline__ void mma_tf32(float c[4], const uint32_t a[4], const uint32_t b[2]) {
    asm volatile(
        "mma.sync.aligned.m16n8k8.row.col.f32.tf32.tf32.f32 "
        "{%0,%1,%2,%3}, {%4,%5,%6,%7}, {%8,%9}, {%0,%1,%2,%3};"
        : "+f"(c[0]), "+f"(c[1]), "+f"(c[2]), "+f"(c[3])
        : "r"(a[0]), "r"(a[1]), "r"(a[2]), "r"(a[3]), "r"(b[0]), "r"(b[1]));
}
#define CP_ASYNC16(dst_u32, src_ptr) \
    asm volatile("cp.async.cg.shared.global [%0], [%1], 16;" :: "r"(dst_u32), "l"(src_ptr))
#define CP_COMMIT() asm volatile("cp.async.commit_group;")
#define CP_WAIT(n)  asm volatile("cp.async.wait_group %0;" :: "n"(n))

// ---------------- LN(s)*w+b, width 512 ----------------
__global__ void __launch_bounds__(128) ln_affine512(
    const float* __restrict__ x, const float* __restrict__ w,
    const float* __restrict__ b, float* __restrict__ out)
{
    int row = blockIdx.x;
    const float4* xr = (const float4*)(x + (size_t)row * CND);
    float4 v = xr[threadIdx.x];
    float s  = v.x + v.y + v.z + v.w;
    float ss = v.x*v.x + v.y*v.y + v.z*v.z + v.w*v.w;
    s = warp_sum(s); ss = warp_sum(ss);
    __shared__ float sh[8];
    int wid = threadIdx.x >> 5, lid = threadIdx.x & 31;
    if (lid == 0) { sh[wid] = s; sh[4 + wid] = ss; }
    __syncthreads();
    s  = sh[0] + sh[1] + sh[2] + sh[3];
    ss = sh[4] + sh[5] + sh[6] + sh[7];
    float mean = s * (1.0f / CND);
    float var  = ss * (1.0f / CND) - mean * mean;
    float rinv = rsqrtf(var + EPSF);
    int d = threadIdx.x * 4;
    float4 wv = *(const float4*)(w + d);
    float4 bv = *(const float4*)(b + d);
    float4 o;
    o.x = (v.x - mean) * rinv * wv.x + bv.x;
    o.y = (v.y - mean) * rinv * wv.y + bv.y;
    o.z = (v.z - mean) * rinv * wv.z + bv.z;
    o.w = (v.w - mean) * rinv * wv.w + bv.w;
    ((float4*)(out + (size_t)row * CND))[threadIdx.x] = o;
}

// ---------------- LN(h)*(1+scale)+shift, width 1024 ----------------
__global__ void __launch_bounds__(256) ln_mod1024(
    const float* __restrict__ x, const float* __restrict__ mod,
    int scale_off, int shift_off, float* __restrict__ out)
{
    int row = blockIdx.x;
    float4 v = ((const float4*)(x + (size_t)row * CD))[threadIdx.x];
    float s  = v.x + v.y + v.z + v.w;
    float ss = v.x*v.x + v.y*v.y + v.z*v.z + v.w*v.w;
    s = warp_sum(s); ss = warp_sum(ss);
    __shared__ float sh[16];
    int wid = threadIdx.x >> 5, lid = threadIdx.x & 31;
    if (lid == 0) { sh[wid] = s; sh[8 + wid] = ss; }
    __syncthreads();
    s = 0.f; ss = 0.f;
#pragma unroll
    for (int i = 0; i < 8; i++) { s += sh[i]; ss += sh[8 + i]; }
    float mean = s * (1.0f / CD);
    float var  = ss * (1.0f / CD) - mean * mean;
    float rinv = rsqrtf(var + EPSF);
    int d = threadIdx.x * 4;
    const float* mrow = mod + (size_t)row * MODW;
    float4 sc = *(const float4*)(mrow + scale_off + d);
    float4 sf = *(const float4*)(mrow + shift_off + d);
    float4 o;
    o.x = ((v.x - mean) * rinv) * (1.0f + sc.x) + sf.x;
    o.y = ((v.y - mean) * rinv) * (1.0f + sc.y) + sf.y;
    o.z = ((v.z - mean) * rinv) * (1.0f + sc.z) + sf.z;
    o.w = ((v.w - mean) * rinv) * (1.0f + sc.w) + sf.w;
    ((float4*)(out + (size_t)row * CD))[threadIdx.x] = o;
}

// ---------------- tf32 NT GEMM, cp.async 2-stage, 2 CTAs/SM ----------------
#define GEMM_SMEM (2 * 2 * 128 * 36 * 4)
template<int EPI>
__global__ void __launch_bounds__(256, 2) gemm_tf32(
    const float* __restrict__ A, const float* __restrict__ W,
    const float* __restrict__ bias, float* __restrict__ C,
    int M, int N, int K,
    const float* __restrict__ res, const float* __restrict__ gate, int gate_off)
{
    extern __shared__ float dynsm[];
    float (*As)[128][36] = (float(*)[128][36])dynsm;
    float (*Ws)[128][36] = (float(*)[128][36])(dynsm + 2 * 128 * 36);

    int bm = blockIdx.y * 128;
    int bn = blockIdx.x * 128;
    int tid  = threadIdx.x;
    int warp = tid >> 5, lane = tid & 31;
    int g = lane >> 2, t = lane & 3;
    int wm = (warp & 1) * 64;
    int wn = (warp >> 1) * 32;

    float acc[4][4][4];
#pragma unroll
    for (int i = 0; i < 4; i++)
#pragma unroll
        for (int j = 0; j < 4; j++)
#pragma unroll
            for (int q = 0; q < 4; q++) acc[i][j][q] = 0.f;

    int ldr = tid >> 3;
    int kv  = (tid & 7) * 4;

#pragma unroll
    for (int r = 0; r < 4; r++) {
        int row = ldr + r * 32;
        uint32_t da = (uint32_t)__cvta_generic_to_shared(&As[0][row][kv]);
        CP_ASYNC16(da, A + (size_t)(bm + row) * K + kv);
        uint32_t dw = (uint32_t)__cvta_generic_to_shared(&Ws[0][row][kv]);
        CP_ASYNC16(dw, W + (size_t)(bn + row) * K + kv);
    }
    CP_COMMIT();

    int nIter = K >> 5;
    for (int it = 0; it < nIter; ++it) {
        if (it + 1 < nIter) {
            int k0n = (it + 1) << 5;
            int stn = (it + 1) & 1;
#pragma unroll
            for (int r = 0; r < 4; r++) {
                int row = ldr + r * 32;
                uint32_t da = (uint32_t)__cvta_generic_to_shared(&As[stn][row][kv]);
                CP_ASYNC16(da, A + (size_t)(bm + row) * K + k0n + kv);
                uint32_t dw = (uint32_t)__cvta_generic_to_shared(&Ws[stn][row][kv]);
                CP_ASYNC16(dw, W + (size_t)(bn + row) * K + k0n + kv);
            }
            CP_COMMIT();
            CP_WAIT(1);
        } else {
            CP_WAIT(0);
        }
        __syncthreads();
        int st = it & 1;
#pragma unroll
        for (int ks = 0; ks < 4; ks++) {
            int kk = ks * 8;
            uint32_t af[4][4];
#pragma unroll
            for (int mt = 0; mt < 4; mt++) {
                int r0 = wm + mt * 16 + g;
                af[mt][0] = __float_as_uint(As[st][r0][kk + t]);
                af[mt][1] = __float_as_uint(As[st][r0 + 8][kk + t]);
                af[mt][2] = __float_as_uint(As[st][r0][kk + t + 4]);
                af[mt][3] = __float_as_uint(As[st][r0 + 8][kk + t + 4]);
            }
            uint32_t bf[4][2];
#pragma unroll
            for (int nt = 0; nt < 4; nt++) {
                int c0 = wn + nt * 8 + g;
                bf[nt][0] = __float_as_uint(Ws[st][c0][kk + t]);
                bf[nt][1] = __float_as_uint(Ws[st][c0][kk + t + 4]);
            }
#pragma unroll
            for (int mt = 0; mt < 4; mt++)
#pragma unroll
                for (int nt = 0; nt < 4; nt++)
                    mma_tf32(acc[mt][nt], af[mt], bf[nt]);
        }
        __syncthreads();
    }

#pragma unroll
    for (int mt = 0; mt < 4; mt++) {
#pragma unroll
        for (int half = 0; half < 2; half++) {
            int row = bm + wm + mt * 16 + g + half * 8;
            float* cr = C + (size_t)row * N;
            const float* rr = (EPI == 2) ? res + (size_t)row * N : nullptr;
            const float* gr = (EPI == 2) ? gate + (size_t)row * MODW + gate_off : nullptr;
#pragma unroll
            for (int nt = 0; nt < 4; nt++) {
                int col = bn + wn + nt * 8 + 2 * t;
                float v0 = acc[mt][nt][half * 2 + 0] + bias[col];
                float v1 = acc[mt][nt][half * 2 + 1] + bias[col + 1];
                if (EPI == 1) {
                    v0 = v0 / (1.0f + expf(-v0));
                    v1 = v1 / (1.0f + expf(-v1));
                }
                if (EPI == 2) {
                    v0 = rr[col]     + v0 * gr[col];
                    v1 = rr[col + 1] + v1 * gr[col + 1];
                }
                float2 o2; o2.x = v0; o2.y = v1;
                *(float2*)(cr + col) = o2;
            }
        }
    }
}

// ---------------- edge bias v3: LN folded into GEMM epilogue, tf32 MMA ----------------
// bias[ij,h] = rinv*( (X @ W2T)[ij,h] - mean*c1[h] ) + c2[h]
// W2T[h,k] = ew[h,k]*lnw[k];  c1[h]=sum_k lnw*ew;  c2[h]=sum_k lnb*ew + eb[h]
__global__ void __launch_bounds__(128) edge_bias_mma(
    const float* __restrict__ p, const float* __restrict__ lnw, const float* __restrict__ lnb,
    const float* __restrict__ ew, const float* __restrict__ eb, float* __restrict__ bias)
{
    __shared__ float rows[128][68];   // raw p rows; (4*row + col) % 32 conflict-free patterns
    __shared__ float W2T[16][68];     // [h][k]
    __shared__ float meanv[128], rinvv[128], c1s[16], c2s[16];
    int tid = threadIdx.x;
    size_t base = (size_t)blockIdx.x * 128;

    // stage p rows, coalesced: 16 threads per row
#pragma unroll
    for (int r = 0; r < 16; r++) {
        int id  = tid + r * 128;
        int row = id >> 4;
        int c4  = (id & 15) * 4;
        *(float4*)&rows[row][c4] = *(const float4*)(p + (base + row) * 64 + c4);
    }
    // W2T
    for (int i = tid; i < 1024; i += 128) {
        int h = i >> 6, k = i & 63;
        W2T[h][k] = ew[i] * lnw[k];
    }
    // c1/c2
    if (tid < 16) {
        float a = 0.f, b2 = 0.f;
        for (int k = 0; k < 64; k++) {
            float e = ew[tid * 64 + k];
            a  += lnw[k] * e;
            b2 += lnb[k] * e;
        }
        c1s[tid] = a;
        c2s[tid] = b2 + eb[tid];
    }
    __syncthreads();

    // per-row stats (thread <-> row)
    {
        float s = 0.f, ss = 0.f;
#pragma unroll
        for (int q = 0; q < 16; q++) {
            float4 x = *(const float4*)&rows[tid][q * 4];
            s  += x.x + x.y + x.z + x.w;
            ss += x.x*x.x + x.y*x.y + x.z*x.z + x.w*x.w;
        }
        float mean = s * (1.0f / 64.0f);
        float var  = ss * (1.0f / 64.0f) - mean * mean;
        meanv[tid] = mean;
        rinvv[tid] = rsqrtf(var + EPSF);
    }
    __syncthreads();

    // MMA: [128x64] @ [16x64]^T -> [128x16]; 4 warps x 2 m-tiles, 2 n-tiles
    int warp = tid >> 5, lane = tid & 31;
    int g = lane >> 2, t = lane & 3;
    float acc[2][2][4];
#pragma unroll
    for (int i = 0; i < 2; i++)
#pragma unroll
        for (int j = 0; j < 2; j++)
#pragma unroll
            for (int q = 0; q < 4; q++) acc[i][j][q] = 0.f;

#pragma unroll
    for (int ks = 0; ks < 8; ks++) {
        int kk = ks * 8;
        uint32_t af[2][4];
#pragma unroll
        for (int mt = 0; mt < 2; mt++) {
            int r0 = warp * 32 + mt * 16 + g;
            af[mt][0] = __float_as_uint(rows[r0][kk + t]);
            af[mt][1] = __float_as_uint(rows[r0 + 8][kk + t]);
            af[mt][2] = __float_as_uint(rows[r0][kk + t + 4]);
            af[mt][3] = __float_as_uint(rows[r0 + 8][kk + t + 4]);
        }
        uint32_t bf[2][2];
#pragma unroll
        for (int nt = 0; nt < 2; nt++) {
            int c0 = nt * 8 + g;
            bf[nt][0] = __float_as_uint(W2T[c0][kk + t]);
            bf[nt][1] = __float_as_uint(W2T[c0][kk + t + 4]);
        }
#pragma unroll
        for (int mt = 0; mt < 2; mt++)
#pragma unroll
            for (int nt = 0; nt < 2; nt++)
                mma_tf32(acc[mt][nt], af[mt], bf[nt]);
    }

    // epilogue: block covers one (b, i) with j = j0..j0+127
    int b  = (int)(base >> 18);
    int ij = (int)(base & 262143);
    int i  = ij >> 9;
    int j0 = ij & 511;
    float* bb = bias + (((size_t)b * 16) * 512 + i) * 512 + j0;
#pragma unroll
    for (int mt = 0; mt < 2; mt++) {
#pragma unroll
        for (int half = 0; half < 2; half++) {
            int rl = warp * 32 + mt * 16 + g + half * 8;
            float m  = meanv[rl];
            float rv = rinvv[rl];
#pragma unroll
            for (int nt = 0; nt < 2; nt++) {
#pragma unroll
                for (int c = 0; c < 2; c++) {
                    int h = nt * 8 + 2 * t + c;
                    float v = rv * (acc[mt][nt][half * 2 + c] - m * c1s[h]) + c2s[h];
                    bb[(size_t)h * 512 * 512 + rl] = v;
                }
            }
        }
    }
}

// ---------------- scores via tf32 MMA: sc = Q@K^T/8 + sc ----------------
__global__ void __launch_bounds__(256) score_mma(
    const float* __restrict__ qkv, float* __restrict__ sc)
{
    __shared__ float Qs[128][36];
    __shared__ float Ks[128][36];
    int bh = blockIdx.z; int b = bh >> 4, h = bh & 15;
    int i0 = blockIdx.y * 128, j0 = blockIdx.x * 128;
    int tid  = threadIdx.x;
    int warp = tid >> 5, lane = tid & 31;
    int g = lane >> 2, t = lane & 3;
    int wm = (warp & 1) * 64;
    int wn = (warp >> 1) * 32;
    const float* qb = qkv + (size_t)(b * CL) * (3 * CD) + h * CDH;
    const float* kb = qb + CD;

    float acc[4][4][4];
#pragma unroll
    for (int i = 0; i < 4; i++)
#pragma unroll
        for (int j = 0; j < 4; j++)
#pragma unroll
            for (int q = 0; q < 4; q++) acc[i][j][q] = 0.f;

#pragma unroll
    for (int k0 = 0; k0 < CDH; k0 += 32) {
#pragma unroll
        for (int r = 0; r < 4; r++) {
            int id  = tid + r * 256;
            int row = id >> 3;
            int kv  = (id & 7) * 4;
            *(float4*)&Qs[row][kv] = *(const float4*)(qb + (size_t)(i0 + row) * (3 * CD) + k0 + kv);
            *(float4*)&Ks[row][kv] = *(const float4*)(kb + (size_t)(j0 + row) * (3 * CD) + k0 + kv);
        }
        __syncthreads();
#pragma unroll
        for (int ks = 0; ks < 4; ks++) {
            int kk = ks * 8;
            uint32_t af[4][4];
#pragma unroll
            for (int mt = 0; mt < 4; mt++) {
                int r0 = wm + mt * 16 + g;
                af[mt][0] = __float_as_uint(Qs[r0][kk + t]);
                af[mt][1] = __float_as_uint(Qs[r0 + 8][kk + t]);
                af[mt][2] = __float_as_uint(Qs[r0][kk + t + 4]);
                af[mt][3] = __float_as_uint(Qs[r0 + 8][kk + t + 4]);
            }
            uint32_t bf[4][2];
#pragma unroll
            for (int nt = 0; nt < 4; nt++) {
                int c0 = wn + nt * 8 + g;
                bf[nt][0] = __float_as_uint(Ks[c0][kk + t]);
                bf[nt][1] = __float_as_uint(Ks[c0][kk + t + 4]);
            }
#pragma unroll
            for (int mt = 0; mt < 4; mt++)
#pragma unroll
                for (int nt = 0; nt < 4; nt++)
                    mma_tf32(acc[mt][nt], af[mt], bf[nt]);
        }
        __syncthreads();
    }

    const float inv8 = 0.125f;
    float* scb = sc + (size_t)bh * CL * CL;
#pragma unroll
    for (int mt = 0; mt < 4; mt++) {
#pragma unroll
        for (int half = 0; half < 2; half++) {
            int row = i0 + wm + mt * 16 + g + half * 8;
            float* cr = scb + (size_t)row * CL;
#pragma unroll
            for (int nt = 0; nt < 4; nt++) {
                int col = j0 + wn + nt * 8 + 2 * t;
                float2 e = *(float2*)(cr + col);
                e.x = fmaf(acc[mt][nt][half * 2 + 0], inv8, e.x);
                e.y = fmaf(acc[mt][nt][half * 2 + 1], inv8, e.y);
                *(float2*)(cr + col) = e;
            }
        }
    }
}

// ---------------- fused softmax + attn@V ----------------
__global__ void __launch_bounds__(256) attnv_mma(
    float* __restrict__ attn, const float* __restrict__ qkv, float* __restrict__ o)
{
    __shared__ float Ps[128][36];
    __shared__ float Vs[32][68];
    __shared__ float invs[128];
    int bh = blockIdx.y; int b = bh >> 4, h = bh & 15;
    int i0 = blockIdx.x * 128;
    int tid  = threadIdx.x;
    int warp = tid >> 5, lane = tid & 31;
    int g = lane >> 2, t = lane & 3;
    float* abase = attn + ((size_t)bh * CL + i0) * CL;
    const float* vbase = qkv + (size_t)(b * CL) * (3 * CD) + 2 * CD + h * CDH;

    // pass 1: softmax (exp in place, invsum to smem)
#pragma unroll
    for (int rr = 0; rr < 16; rr++) {
        int row = warp * 16 + rr;
        float* rp = abase + (size_t)row * CL;
        float4 v[4];
        float m = -1e30f;
#pragma unroll
        for (int c = 0; c < 4; c++) {
            v[c] = *(float4*)(rp + c * 128 + lane * 4);
            m = fmaxf(m, fmaxf(fmaxf(v[c].x, v[c].y), fmaxf(v[c].z, v[c].w)));
        }
        m = warp_max(m);
        float su = 0.f;
#pragma unroll
        for (int c = 0; c < 4; c++) {
            v[c].x = expf(v[c].x - m); v[c].y = expf(v[c].y - m);
            v[c].z = expf(v[c].z - m); v[c].w = expf(v[c].w - m);
            su += v[c].x + v[c].y + v[c].z + v[c].w;
            *(float4*)(rp + c * 128 + lane * 4) = v[c];
        }
        su = warp_sum(su);
        if (lane == 0) invs[row] = 1.0f / su;
    }
    __syncthreads();

    float acc[2][4][4];
#pragma unroll
    for (int i = 0; i < 2; i++)
#pragma unroll
        for (int j = 0; j < 4; j++)
#pragma unroll
            for (int q = 0; q < 4; q++) acc[i][j][q] = 0.f;

    int wmm = (warp & 3) * 32;
    int wnn = (warp >> 2) * 32;
    for (int j0 = 0; j0 < CL; j0 += 32) {
#pragma unroll
        for (int r = 0; r < 4; r++) {
            int id  = tid + r * 256;
            int row = id >> 3;
            int jv  = (id & 7) * 4;
            *(float4*)&Ps[row][jv] = *(const float4*)(abase + (size_t)row * CL + j0 + jv);
        }
#pragma unroll
        for (int r = 0; r < 2; r++) {
            int id = tid + r * 256;
            int kk = id >> 4;
            int dv = (id & 15) * 4;
            *(float4*)&Vs[kk][dv] = *(const float4*)(vbase + (size_t)(j0 + kk) * (3 * CD) + dv);
        }
        __syncthreads();
#pragma unroll
        for (int ks = 0; ks < 4; ks++) {
            int kk = ks * 8;
            uint32_t af[2][4];
#pragma unroll
            for (int mt = 0; mt < 2; mt++) {
                int r0 = wmm + mt * 16 + g;
                af[mt][0] = __float_as_uint(Ps[r0][kk + t]);
                af[mt][1] = __float_as_uint(Ps[r0 + 8][kk + t]);
                af[mt][2] = __float_as_uint(Ps[r0][kk + t + 4]);
                af[mt][3] = __float_as_uint(Ps[r0 + 8][kk + t + 4]);
            }
            uint32_t bf[4][2];
#pragma unroll
            for (int nt = 0; nt < 4; nt++) {
                int c0 = wnn + nt * 8 + g;
                bf[nt][0] = __float_as_uint(Vs[kk + t][c0]);
                bf[nt][1] = __float_as_uint(Vs[kk + t + 4][c0]);
            }
#pragma unroll
            for (int mt = 0; mt < 2; mt++)
#pragma unroll
                for (int nt = 0; nt < 4; nt++)
                    mma_tf32(acc[mt][nt], af[mt], bf[nt]);
        }
        __syncthreads();
    }

#pragma unroll
    for (int mt = 0; mt < 2; mt++) {
#pragma unroll
        for (int half = 0; half < 2; half++) {
            int li = wmm + mt * 16 + g + half * 8;
            float sc = invs[li];
            int i = i0 + li;
            float* orow = o + (size_t)(b * CL + i) * CD + h * CDH;
#pragma unroll
            for (int nt = 0; nt < 4; nt++) {
                int d = wnn + nt * 8 + 2 * t;
                float2 w;
                w.x = acc[mt][nt][half * 2 + 0] * sc;
                w.y = acc[mt][nt][half * 2 + 1] * sc;
                *(float2*)(orow + d) = w;
            }
        }
    }
}

// ---------------- launch ----------------
extern "C" void kernel_launch(void* const* d_in, const int* in_sizes, int n_in,
                              void* d_out, int out_size)
{
    const float* h_in  = (const float*)d_in[0];
    const float* s_in  = (const float*)d_in[1];
    const float* p_in  = (const float*)d_in[2];
    const float* aln_w = (const float*)d_in[3];
    const float* aln_b = (const float*)d_in[4];
    const float* aw1   = (const float*)d_in[5];
    const float* ab1   = (const float*)d_in[6];
    const float* aw2   = (const float*)d_in[7];
    const float* ab2   = (const float*)d_in[8];
    const float* eln_w = (const float*)d_in[9];
    const float* eln_b = (const float*)d_in[10];
    const float* ew    = (const float*)d_in[11];
    const float* eb    = (const float*)d_in[12];
    const float* in_w  = (const float*)d_in[13];
    const float* in_b  = (const float*)d_in[14];
    const float* out_w = (const float*)d_in[15];
    const float* out_b = (const float*)d_in[16];
    const float* mw1   = (const float*)d_in[17];
    const float* mb1   = (const float*)d_in[18];
    const float* mw2   = (const float*)d_in[19];
    const float* mb2   = (const float*)d_in[20];
    float* out = (float*)d_out;

    float *sln, *t1, *mod, *scores, *x, *qkv, *o, *h2, *t2;
    cudaGetSymbolAddress((void**)&sln,    g_sln);
    cudaGetSymbolAddress((void**)&t1,     g_t1);
    cudaGetSymbolAddress((void**)&mod,    g_mod);
    cudaGetSymbolAddress((void**)&scores, g_scores);
    cudaGetSymbolAddress((void**)&x,      g_x);
    cudaGetSymbolAddress((void**)&qkv,    g_qkv);
    cudaGetSymbolAddress((void**)&o,      g_o);
    cudaGetSymbolAddress((void**)&h2,     g_h2);
    cudaGetSymbolAddress((void**)&t2,     g_t2);

    cudaFuncSetAttribute(gemm_tf32<0>, cudaFuncAttributeMaxDynamicSharedMemorySize, GEMM_SMEM);
    cudaFuncSetAttribute(gemm_tf32<1>, cudaFuncAttributeMaxDynamicSharedMemorySize, GEMM_SMEM);
    cudaFuncSetAttribute(gemm_tf32<2>, cudaFuncAttributeMaxDynamicSharedMemorySize, GEMM_SMEM);

    // adaLN modulation chain
    ln_affine512<<<NTOK, 128>>>(s_in, aln_w, aln_b, sln);
    gemm_tf32<1><<<dim3(CND / 128, NTOK / 128), 256, GEMM_SMEM>>>(sln, aw1, ab1, t1,
        NTOK, CND, CND, nullptr, nullptr, 0);
    gemm_tf32<0><<<dim3(MODW / 128, NTOK / 128), 256, GEMM_SMEM>>>(t1, aw2, ab2, mod,
        NTOK, MODW, CND, nullptr, nullptr, 0);

    // edge bias (writes into scores buffer)
    edge_bias_mma<<<(CB * CL * CL) / 128, 128>>>(p_in, eln_w, eln_b, ew, eb, scores);

    // attention branch
    ln_mod1024<<<NTOK, 256>>>(h_in, mod, /*scale*/CD, /*shift*/0, x);
    gemm_tf32<0><<<dim3(3 * CD / 128, NTOK / 128), 256, GEMM_SMEM>>>(x, in_w, in_b, qkv,
        NTOK, 3 * CD, CD, nullptr, nullptr, 0);
    score_mma<<<dim3(4, 4, CB * CH), 256>>>(qkv, scores);
    attnv_mma<<<dim3(4, CB * CH), 256>>>(scores, qkv, o);
    gemm_tf32<2><<<dim3(CD / 128, NTOK / 128), 256, GEMM_SMEM>>>(o, out_w, out_b, h2,
        NTOK, CD, CD, h_in, mod, 2 * CD);

    // gated MLP branch
    ln_mod1024<<<NTOK, 256>>>(h2, mod, /*scale*/4 * CD, /*shift*/3 * CD, x);
    gemm_tf32<1><<<dim3(CMLP / 128, NTOK / 128), 256, GEMM_SMEM>>>(x, mw1, mb1, t2,
        NTOK, CMLP, CD, nullptr, nullptr, 0);
    gemm_tf32<2><<<dim3(CD / 128, NTOK / 128), 256, GEMM_SMEM>>>(t2, mw2, mb2, out,
        NTOK, CD, CMLP, h2, mod, 5 * CD);
}

// round 7
// speedup vs baseline: 1.0487x; 1.0487x over previous
#include <cuda_runtime.h>
#include <cuda_fp16.h>
#include <math.h>
#include <stdint.h>

// Problem constants
#define CB   4
#define CL   512
#define CD   1024
#define CND  512
#define CED  64
#define CH   16
#define CMLP 2048
#define CDH  64
#define NTOK (CB*CL)        // 2048
#define MODW (6*CD)         // 6144
#define EPSF 1e-5f

// ---------------- scratch ----------------
__device__ float g_sln[NTOK*CND];
__device__ float g_t1[NTOK*CND];
__device__ float g_mod[NTOK*MODW];
__device__ float g_scores[(size_t)CB*CH*CL*CL];
__device__ float g_x[NTOK*CD];
__device__ float g_qkv[NTOK*3*CD];
__device__ float g_o[NTOK*CD];
__device__ float g_h2[NTOK*CD];
__device__ float g_t2[NTOK*CMLP];

// ---------------- utils ----------------
__device__ __forceinline__ float warp_sum(float v) {
#pragma unroll
    for (int o = 16; o > 0; o >>= 1) v += __shfl_xor_sync(0xffffffffu, v, o);
    return v;
}
__device__ __forceinline__ float warp_max(float v) {
#pragma unroll
    for (int o = 16; o > 0; o >>= 1) v = fmaxf(v, __shfl_xor_sync(0xffffffffu, v, o));
    return v;
}
__device__ __forceinline__ void mma_tf32(float c[4], const uint32_t a[4], const uint32_t b[2]) {
    asm volatile(
        "mma.sync.aligned.m16n8k8.row.col.f32.tf32.tf32.f32 "
        "{%0,%1,%2,%3}, {%4,%5,%6,%7}, {%8,%9}, {%0,%1,%2,%3};"
        : "+f"(c[0]), "+f"(c[1]), "+f"(c[2]), "+f"(c[3])
        : "r"(a[0]), "r"(a[1]), "r"(a[2]), "r"(a[3]), "r"(b[0]), "r"(b[1]));
}
__device__ __forceinline__ void mma_fp16(float c[4], const uint32_t a[4], const uint32_t b[2]) {
    asm volatile(
        "mma.sync.aligned.m16n8k16.row.col.f32.f16.f16.f32 "
        "{%0,%1,%2,%3}, {%4,%5,%6,%7}, {%8,%9}, {%0,%1,%2,%3};"
        : "+f"(c[0]), "+f"(c[1]), "+f"(c[2]), "+f"(c[3])
        : "r"(a[0]), "r"(a[1]), "r"(a[2]), "r"(a[3]), "r"(b[0]), "r"(b[1]));
}
__device__ __forceinline__ uint32_t pack_h2(float lo, float hi) {
    __half2 h = __floats2half2_rn(lo, hi);
    return *(uint32_t*)&h;
}

// ---------------- LN(s)*w+b, width 512 ----------------
__global__ void __launch_bounds__(128) ln_affine512(
    const float* __restrict__ x, const float* __restrict__ w,
    const float* __restrict__ b, float* __restrict__ out)
{
    int row = blockIdx.x;
    const float4* xr = (const float4*)(x + (size_t)row * CND);
    float4 v = xr[threadIdx.x];
    float s  = v.x + v.y + v.z + v.w;
    float ss = v.x*v.x + v.y*v.y + v.z*v.z + v.w*v.w;
    s = warp_sum(s); ss = warp_sum(ss);
    __shared__ float sh[8];
    int wid = threadIdx.x >> 5, lid = threadIdx.x & 31;
    if (lid == 0) { sh[wid] = s; sh[4 + wid] = ss; }
    __syncthreads();
    s  = sh[0] + sh[1] + sh[2] + sh[3];
    ss = sh[4] + sh[5] + sh[6] + sh[7];
    float mean = s * (1.0f / CND);
    float var  = ss * (1.0f / CND) - mean * mean;
    float rinv = rsqrtf(var + EPSF);
    int d = threadIdx.x * 4;
    float4 wv = *(const float4*)(w + d);
    float4 bv = *(const float4*)(b + d);
    float4 o;
    o.x = (v.x - mean) * rinv * wv.x + bv.x;
    o.y = (v.y - mean) * rinv * wv.y + bv.y;
    o.z = (v.z - mean) * rinv * wv.z + bv.z;
    o.w = (v.w - mean) * rinv * wv.w + bv.w;
    ((float4*)(out + (size_t)row * CND))[threadIdx.x] = o;
}

// ---------------- LN(h)*(1+scale)+shift, width 1024 ----------------
__global__ void __launch_bounds__(256) ln_mod1024(
    const float* __restrict__ x, const float* __restrict__ mod,
    int scale_off, int shift_off, float* __restrict__ out)
{
    int row = blockIdx.x;
    float4 v = ((const float4*)(x + (size_t)row * CD))[threadIdx.x];
    float s  = v.x + v.y + v.z + v.w;
    float ss = v.x*v.x + v.y*v.y + v.z*v.z + v.w*v.w;
    s = warp_sum(s); ss = warp_sum(ss);
    __shared__ float sh[16];
    int wid = threadIdx.x >> 5, lid = threadIdx.x & 31;
    if (lid == 0) { sh[wid] = s; sh[8 + wid] = ss; }
    __syncthreads();
    s = 0.f; ss = 0.f;
#pragma unroll
    for (int i = 0; i < 8; i++) { s += sh[i]; ss += sh[8 + i]; }
    float mean = s * (1.0f / CD);
    float var  = ss * (1.0f / CD) - mean * mean;
    float rinv = rsqrtf(var + EPSF);
    int d = threadIdx.x * 4;
    const float* mrow = mod + (size_t)row * MODW;
    float4 sc = *(const float4*)(mrow + scale_off + d);
    float4 sf = *(const float4*)(mrow + shift_off + d);
    float4 o;
    o.x = ((v.x - mean) * rinv) * (1.0f + sc.x) + sf.x;
    o.y = ((v.y - mean) * rinv) * (1.0f + sc.y) + sf.y;
    o.z = ((v.z - mean) * rinv) * (1.0f + sc.z) + sf.z;
    o.w = ((v.w - mean) * rinv) * (1.0f + sc.w) + sf.w;
    ((float4*)(out + (size_t)row * CD))[threadIdx.x] = o;
}

// ---------------- fp16 NT GEMM (m16n8k16, fp32 accum) ----------------
// Block 128x128x32, 256 threads, 8 warps (2x4), warp tile 64x32.
// Smem: half2-packed uint32 [128][20] per operand, double buffered.
// Reg double-buffer staging: LDG next tile -> compute -> STS next.
#define GEMM_SMEM_H (2 * 2 * 128 * 20 * 4)
template<int EPI>
__global__ void __launch_bounds__(256, 2) gemm_fp16(
    const float* __restrict__ A, const float* __restrict__ W,
    const float* __restrict__ bias, float* __restrict__ C,
    int M, int N, int K,
    const float* __restrict__ res, const float* __restrict__ gate, int gate_off)
{
    extern __shared__ uint32_t dynh[];
    uint32_t* As = dynh;                    // [2][128][20]
    uint32_t* Ws = dynh + 2 * 128 * 20;     // [2][128][20]

    int bm = blockIdx.y * 128;
    int bn = blockIdx.x * 128;
    int tid  = threadIdx.x;
    int warp = tid >> 5, lane = tid & 31;
    int g = lane >> 2, t = lane & 3;
    int wm = (warp & 1) * 64;
    int wn = (warp >> 1) * 32;

    float acc[4][4][4];
#pragma unroll
    for (int i = 0; i < 4; i++)
#pragma unroll
        for (int j = 0; j < 4; j++)
#pragma unroll
            for (int q = 0; q < 4; q++) acc[i][j][q] = 0.f;

    int ldr = tid >> 3;              // base row 0..31
    int kv  = (tid & 7) * 4;         // float col 0..28
    int jp  = kv >> 1;               // pair col (even)

    float4 ra[4], rw[4];
    // prologue: load tile 0, convert, store stage 0
#pragma unroll
    for (int r = 0; r < 4; r++) {
        int row = ldr + r * 32;
        ra[r] = *(const float4*)(A + (size_t)(bm + row) * K + kv);
        rw[r] = *(const float4*)(W + (size_t)(bn + row) * K + kv);
    }
#pragma unroll
    for (int r = 0; r < 4; r++) {
        int row = ldr + r * 32;
        uint2 ua; ua.x = pack_h2(ra[r].x, ra[r].y); ua.y = pack_h2(ra[r].z, ra[r].w);
        *(uint2*)&As[(size_t)row * 20 + jp] = ua;
        uint2 uw; uw.x = pack_h2(rw[r].x, rw[r].y); uw.y = pack_h2(rw[r].z, rw[r].w);
        *(uint2*)&Ws[(size_t)row * 20 + jp] = uw;
    }
    __syncthreads();

    int nIter = K >> 5;
    for (int it = 0; it < nIter; ++it) {
        if (it + 1 < nIter) {
            int k0n = (it + 1) << 5;
#pragma unroll
            for (int r = 0; r < 4; r++) {
                int row = ldr + r * 32;
                ra[r] = *(const float4*)(A + (size_t)(bm + row) * K + k0n + kv);
                rw[r] = *(const float4*)(W + (size_t)(bn + row) * K + k0n + kv);
            }
        }
        int st = it & 1;
        const uint32_t* Ab = As + (size_t)st * 128 * 20;
        const uint32_t* Wb = Ws + (size_t)st * 128 * 20;
#pragma unroll
        for (int ks = 0; ks < 2; ks++) {
            int kp = ks * 8;
            uint32_t af[4][4];
#pragma unroll
            for (int mt = 0; mt < 4; mt++) {
                int r0 = wm + mt * 16 + g;
                af[mt][0] = Ab[(size_t)r0 * 20 + kp + t];
                af[mt][1] = Ab[(size_t)(r0 + 8) * 20 + kp + t];
                af[mt][2] = Ab[(size_t)r0 * 20 + kp + t + 4];
                af[mt][3] = Ab[(size_t)(r0 + 8) * 20 + kp + t + 4];
            }
            uint32_t bf[4][2];
#pragma unroll
            for (int nt = 0; nt < 4; nt++) {
                int c0 = wn + nt * 8 + g;
                bf[nt][0] = Wb[(size_t)c0 * 20 + kp + t];
                bf[nt][1] = Wb[(size_t)c0 * 20 + kp + t + 4];
            }
#pragma unroll
            for (int mt = 0; mt < 4; mt++)
#pragma unroll
                for (int nt = 0; nt < 4; nt++)
                    mma_fp16(acc[mt][nt], af[mt], bf[nt]);
        }
        __syncthreads();
        if (it + 1 < nIter) {
            int stn = (it + 1) & 1;
            uint32_t* An = As + (size_t)stn * 128 * 20;
            uint32_t* Wn = Ws + (size_t)stn * 128 * 20;
#pragma unroll
            for (int r = 0; r < 4; r++) {
                int row = ldr + r * 32;
                uint2 ua; ua.x = pack_h2(ra[r].x, ra[r].y); ua.y = pack_h2(ra[r].z, ra[r].w);
                *(uint2*)&An[(size_t)row * 20 + jp] = ua;
                uint2 uw; uw.x = pack_h2(rw[r].x, rw[r].y); uw.y = pack_h2(rw[r].z, rw[r].w);
                *(uint2*)&Wn[(size_t)row * 20 + jp] = uw;
            }
            __syncthreads();
        }
    }

#pragma unroll
    for (int mt = 0; mt < 4; mt++) {
#pragma unroll
        for (int half = 0; half < 2; half++) {
            int row = bm + wm + mt * 16 + g + half * 8;
            float* cr = C + (size_t)row * N;
            const float* rr = (EPI == 2) ? res + (size_t)row * N : nullptr;
            const float* gr = (EPI == 2) ? gate + (size_t)row * MODW + gate_off : nullptr;
#pragma unroll
            for (int nt = 0; nt < 4; nt++) {
                int col = bn + wn + nt * 8 + 2 * t;
                float v0 = acc[mt][nt][half * 2 + 0] + bias[col];
                float v1 = acc[mt][nt][half * 2 + 1] + bias[col + 1];
                if (EPI == 1) {
                    v0 = v0 / (1.0f + expf(-v0));
                    v1 = v1 / (1.0f + expf(-v1));
                }
                if (EPI == 2) {
                    v0 = rr[col]     + v0 * gr[col];
                    v1 = rr[col + 1] + v1 * gr[col + 1];
                }
                float2 o2; o2.x = v0; o2.y = v1;
                *(float2*)(cr + col) = o2;
            }
        }
    }
}

// ---------------- edge bias v4: MMA + smem-transposed coalesced stores ----------------
// bias[ij,h] = rinv*( (X @ W2T)[ij,h] - mean*c1[h] ) + c2[h]
__global__ void __launch_bounds__(128) edge_bias_mma(
    const float* __restrict__ p, const float* __restrict__ lnw, const float* __restrict__ lnb,
    const float* __restrict__ ew, const float* __restrict__ eb, float* __restrict__ bias)
{
    __shared__ float rows[128][68];
    __shared__ float W2T[16][68];
    __shared__ float meanv[128], rinvv[128], c1s[16], c2s[16];
    int tid = threadIdx.x;
    size_t base = (size_t)blockIdx.x * 128;

#pragma unroll
    for (int r = 0; r < 16; r++) {
        int id  = tid + r * 128;
        int row = id >> 4;
        int c4  = (id & 15) * 4;
        *(float4*)&rows[row][c4] = *(const float4*)(p + (base + row) * 64 + c4);
    }
    for (int i = tid; i < 1024; i += 128) {
        int h = i >> 6, k = i & 63;
        W2T[h][k] = ew[i] * lnw[k];
    }
    if (tid < 16) {
        float a = 0.f, b2 = 0.f;
        for (int k = 0; k < 64; k++) {
            float e = ew[tid * 64 + k];
            a  += lnw[k] * e;
            b2 += lnb[k] * e;
        }
        c1s[tid] = a;
        c2s[tid] = b2 + eb[tid];
    }
    __syncthreads();

    {
        float s = 0.f, ss = 0.f;
#pragma unroll
        for (int q = 0; q < 16; q++) {
            float4 x = *(const float4*)&rows[tid][q * 4];
            s  += x.x + x.y + x.z + x.w;
            ss += x.x*x.x + x.y*x.y + x.z*x.z + x.w*x.w;
        }
        float mean = s * (1.0f / 64.0f);
        float var  = ss * (1.0f / 64.0f) - mean * mean;
        meanv[tid] = mean;
        rinvv[tid] = rsqrtf(var + EPSF);
    }
    __syncthreads();

    int warp = tid >> 5, lane = tid & 31;
    int g = lane >> 2, t = lane & 3;
    float acc[2][2][4];
#pragma unroll
    for (int i = 0; i < 2; i++)
#pragma unroll
        for (int j = 0; j < 2; j++)
#pragma unroll
            for (int q = 0; q < 4; q++) acc[i][j][q] = 0.f;

#pragma unroll
    for (int ks = 0; ks < 8; ks++) {
        int kk = ks * 8;
        uint32_t af[2][4];
#pragma unroll
        for (int mt = 0; mt < 2; mt++) {
            int r0 = warp * 32 + mt * 16 + g;
            af[mt][0] = __float_as_uint(rows[r0][kk + t]);
            af[mt][1] = __float_as_uint(rows[r0 + 8][kk + t]);
            af[mt][2] = __float_as_uint(rows[r0][kk + t + 4]);
            af[mt][3] = __float_as_uint(rows[r0 + 8][kk + t + 4]);
        }
        uint32_t bf[2][2];
#pragma unroll
        for (int nt = 0; nt < 2; nt++) {
            int c0 = nt * 8 + g;
            bf[nt][0] = __float_as_uint(W2T[c0][kk + t]);
            bf[nt][1] = __float_as_uint(W2T[c0][kk + t + 4]);
        }
#pragma unroll
        for (int mt = 0; mt < 2; mt++)
#pragma unroll
            for (int nt = 0; nt < 2; nt++)
                mma_tf32(acc[mt][nt], af[mt], bf[nt]);
    }

    // transpose through smem (reuse rows[]) -> coalesced per-plane stores
    float* outT = &rows[0][0];   // [16][132] view, 2112 floats < 128*68
    __syncthreads();             // all frag reads of rows[] done
#pragma unroll
    for (int mt = 0; mt < 2; mt++) {
#pragma unroll
        for (int half = 0; half < 2; half++) {
            int rl = warp * 32 + mt * 16 + g + half * 8;
            float m  = meanv[rl];
            float rv = rinvv[rl];
#pragma unroll
            for (int nt = 0; nt < 2; nt++) {
#pragma unroll
                for (int c = 0; c < 2; c++) {
                    int h = nt * 8 + 2 * t + c;
                    outT[h * 132 + rl] = rv * (acc[mt][nt][half * 2 + c] - m * c1s[h]) + c2s[h];
                }
            }
        }
    }
    __syncthreads();

    int b  = (int)(base >> 18);
    int ij = (int)(base & 262143);
    int i  = ij >> 9;
    int j0 = ij & 511;
    float* bb = bias + (((size_t)b * 16) * 512 + i) * 512 + j0;
    int h  = tid >> 3;           // 0..15
    int jq = (tid & 7) * 16;     // 0..112
#pragma unroll
    for (int c = 0; c < 4; c++) {
        float4 v = *(float4*)&outT[h * 132 + jq + c * 4];
        *(float4*)(bb + (size_t)h * 512 * 512 + jq + c * 4) = v;
    }
}

// ---------------- scores via tf32 MMA: sc = Q@K^T/8 + sc ----------------
__global__ void __launch_bounds__(256) score_mma(
    const float* __restrict__ qkv, float* __restrict__ sc)
{
    __shared__ float Qs[128][36];
    __shared__ float Ks[128][36];
    int bh = blockIdx.z; int b = bh >> 4, h = bh & 15;
    int i0 = blockIdx.y * 128, j0 = blockIdx.x * 128;
    int tid  = threadIdx.x;
    int warp = tid >> 5, lane = tid & 31;
    int g = lane >> 2, t = lane & 3;
    int wm = (warp & 1) * 64;
    int wn = (warp >> 1) * 32;
    const float* qb = qkv + (size_t)(b * CL) * (3 * CD) + h * CDH;
    const float* kb = qb + CD;

    float acc[4][4][4];
#pragma unroll
    for (int i = 0; i < 4; i++)
#pragma unroll
        for (int j = 0; j < 4; j++)
#pragma unroll
            for (int q = 0; q < 4; q++) acc[i][j][q] = 0.f;

#pragma unroll
    for (int k0 = 0; k0 < CDH; k0 += 32) {
#pragma unroll
        for (int r = 0; r < 4; r++) {
            int id  = tid + r * 256;
            int row = id >> 3;
            int kv  = (id & 7) * 4;
            *(float4*)&Qs[row][kv] = *(const float4*)(qb + (size_t)(i0 + row) * (3 * CD) + k0 + kv);
            *(float4*)&Ks[row][kv] = *(const float4*)(kb + (size_t)(j0 + row) * (3 * CD) + k0 + kv);
        }
        __syncthreads();
#pragma unroll
        for (int ks = 0; ks < 4; ks++) {
            int kk = ks * 8;
            uint32_t af[4][4];
#pragma unroll
            for (int mt = 0; mt < 4; mt++) {
                int r0 = wm + mt * 16 + g;
                af[mt][0] = __float_as_uint(Qs[r0][kk + t]);
                af[mt][1] = __float_as_uint(Qs[r0 + 8][kk + t]);
                af[mt][2] = __float_as_uint(Qs[r0][kk + t + 4]);
                af[mt][3] = __float_as_uint(Qs[r0 + 8][kk + t + 4]);
            }
            uint32_t bf[4][2];
#pragma unroll
            for (int nt = 0; nt < 4; nt++) {
                int c0 = wn + nt * 8 + g;
                bf[nt][0] = __float_as_uint(Ks[c0][kk + t]);
                bf[nt][1] = __float_as_uint(Ks[c0][kk + t + 4]);
            }
#pragma unroll
            for (int mt = 0; mt < 4; mt++)
#pragma unroll
                for (int nt = 0; nt < 4; nt++)
                    mma_tf32(acc[mt][nt], af[mt], bf[nt]);
        }
        __syncthreads();
    }

    const float inv8 = 0.125f;
    float* scb = sc + (size_t)bh * CL * CL;
#pragma unroll
    for (int mt = 0; mt < 4; mt++) {
#pragma unroll
        for (int half = 0; half < 2; half++) {
            int row = i0 + wm + mt * 16 + g + half * 8;
            float* cr = scb + (size_t)row * CL;
#pragma unroll
            for (int nt = 0; nt < 4; nt++) {
                int col = j0 + wn + nt * 8 + 2 * t;
                float2 e = *(float2*)(cr + col);
                e.x = fmaf(acc[mt][nt][half * 2 + 0], inv8, e.x);
                e.y = fmaf(acc[mt][nt][half * 2 + 1], inv8, e.y);
                *(float2*)(cr + col) = e;
            }
        }
    }
}

// ---------------- fused softmax + attn@V ----------------
__global__ void __launch_bounds__(256) attnv_mma(
    float* __restrict__ attn, const float* __restrict__ qkv, float* __restrict__ o)
{
    __shared__ float Ps[128][36];
    __shared__ float Vs[32][68];
    __shared__ float invs[128];
    int bh = blockIdx.y; int b = bh >> 4, h = bh & 15;
    int i0 = blockIdx.x * 128;
    int tid  = threadIdx.x;
    int warp = tid >> 5, lane = tid & 31;
    int g = lane >> 2, t = lane & 3;
    float* abase = attn + ((size_t)bh * CL + i0) * CL;
    const float* vbase = qkv + (size_t)(b * CL) * (3 * CD) + 2 * CD + h * CDH;

#pragma unroll
    for (int rr = 0; rr < 16; rr++) {
        int row = warp * 16 + rr;
        float* rp = abase + (size_t)row * CL;
        float4 v[4];
        float m = -1e30f;
#pragma unroll
        for (int c = 0; c < 4; c++) {
            v[c] = *(float4*)(rp + c * 128 + lane * 4);
            m = fmaxf(m, fmaxf(fmaxf(v[c].x, v[c].y), fmaxf(v[c].z, v[c].w)));
        }
        m = warp_max(m);
        float su = 0.f;
#pragma unroll
        for (int c = 0; c < 4; c++) {
            v[c].x = expf(v[c].x - m); v[c].y = expf(v[c].y - m);
            v[c].z = expf(v[c].z - m); v[c].w = expf(v[c].w - m);
            su += v[c].x + v[c].y + v[c].z + v[c].w;
            *(float4*)(rp + c * 128 + lane * 4) = v[c];
        }
        su = warp_sum(su);
        if (lane == 0) invs[row] = 1.0f / su;
    }
    __syncthreads();

    float acc[2][4][4];
#pragma unroll
    for (int i = 0; i < 2; i++)
#pragma unroll
        for (int j = 0; j < 4; j++)
#pragma unroll
            for (int q = 0; q < 4; q++) acc[i][j][q] = 0.f;

    int wmm = (warp & 3) * 32;
    int wnn = (warp >> 2) * 32;
    for (int j0 = 0; j0 < CL; j0 += 32) {
#pragma unroll
        for (int r = 0; r < 4; r++) {
            int id  = tid + r * 256;
            int row = id >> 3;
            int jv  = (id & 7) * 4;
            *(float4*)&Ps[row][jv] = *(const float4*)(abase + (size_t)row * CL + j0 + jv);
        }
#pragma unroll
        for (int r = 0; r < 2; r++) {
            int id = tid + r * 256;
            int kk = id >> 4;
            int dv = (id & 15) * 4;
            *(float4*)&Vs[kk][dv] = *(const float4*)(vbase + (size_t)(j0 + kk) * (3 * CD) + dv);
        }
        __syncthreads();
#pragma unroll
        for (int ks = 0; ks < 4; ks++) {
            int kk = ks * 8;
            uint32_t af[2][4];
#pragma unroll
            for (int mt = 0; mt < 2; mt++) {
                int r0 = wmm + mt * 16 + g;
                af[mt][0] = __float_as_uint(Ps[r0][kk + t]);
                af[mt][1] = __float_as_uint(Ps[r0 + 8][kk + t]);
                af[mt][2] = __float_as_uint(Ps[r0][kk + t + 4]);
                af[mt][3] = __float_as_uint(Ps[r0 + 8][kk + t + 4]);
            }
            uint32_t bf[4][2];
#pragma unroll
            for (int nt = 0; nt < 4; nt++) {
                int c0 = wnn + nt * 8 + g;
                bf[nt][0] = __float_as_uint(Vs[kk + t][c0]);
                bf[nt][1] = __float_as_uint(Vs[kk + t + 4][c0]);
            }
#pragma unroll
            for (int mt = 0; mt < 2; mt++)
#pragma unroll
                for (int nt = 0; nt < 4; nt++)
                    mma_tf32(acc[mt][nt], af[mt], bf[nt]);
        }
        __syncthreads();
    }

#pragma unroll
    for (int mt = 0; mt < 2; mt++) {
#pragma unroll
        for (int half = 0; half < 2; half++) {
            int li = wmm + mt * 16 + g + half * 8;
            float sc = invs[li];
            int i = i0 + li;
            float* orow = o + (size_t)(b * CL + i) * CD + h * CDH;
#pragma unroll
            for (int nt = 0; nt < 4; nt++) {
                int d = wnn + nt * 8 + 2 * t;
                float2 w;
                w.x = acc[mt][nt][half * 2 + 0] * sc;
                w.y = acc[mt][nt][half * 2 + 1] * sc;
                *(float2*)(orow + d) = w;
            }
        }
    }
}

// ---------------- launch ----------------
extern "C" void kernel_launch(void* const* d_in, const int* in_sizes, int n_in,
                              void* d_out, int out_size)
{
    const float* h_in  = (const float*)d_in[0];
    const float* s_in  = (const float*)d_in[1];
    const float* p_in  = (const float*)d_in[2];
    const float* aln_w = (const float*)d_in[3];
    const float* aln_b = (const float*)d_in[4];
    const float* aw1   = (const float*)d_in[5];
    const float* ab1   = (const float*)d_in[6];
    const float* aw2   = (const float*)d_in[7];
    const float* ab2   = (const float*)d_in[8];
    const float* eln_w = (const float*)d_in[9];
    const float* eln_b = (const float*)d_in[10];
    const float* ew    = (const float*)d_in[11];
    const float* eb    = (const float*)d_in[12];
    const float* in_w  = (const float*)d_in[13];
    const float* in_b  = (const float*)d_in[14];
    const float* out_w = (const float*)d_in[15];
    const float* out_b = (const float*)d_in[16];
    const float* mw1   = (const float*)d_in[17];
    const float* mb1   = (const float*)d_in[18];
    const float* mw2   = (const float*)d_in[19];
    const float* mb2   = (const float*)d_in[20];
    float* out = (float*)d_out;

    float *sln, *t1, *mod, *scores, *x, *qkv, *o, *h2, *t2;
    cudaGetSymbolAddress((void**)&sln,    g_sln);
    cudaGetSymbolAddress((void**)&t1,     g_t1);
    cudaGetSymbolAddress((void**)&mod,    g_mod);
    cudaGetSymbolAddress((void**)&scores, g_scores);
    cudaGetSymbolAddress((void**)&x,      g_x);
    cudaGetSymbolAddress((void**)&qkv,    g_qkv);
    cudaGetSymbolAddress((void**)&o,      g_o);
    cudaGetSymbolAddress((void**)&h2,     g_h2);
    cudaGetSymbolAddress((void**)&t2,     g_t2);

    cudaFuncSetAttribute(gemm_fp16<0>, cudaFuncAttributeMaxDynamicSharedMemorySize, GEMM_SMEM_H);
    cudaFuncSetAttribute(gemm_fp16<1>, cudaFuncAttributeMaxDynamicSharedMemorySize, GEMM_SMEM_H);
    cudaFuncSetAttribute(gemm_fp16<2>, cudaFuncAttributeMaxDynamicSharedMemorySize, GEMM_SMEM_H);

    // adaLN modulation chain
    ln_affine512<<<NTOK, 128>>>(s_in, aln_w, aln_b, sln);
    gemm_fp16<1><<<dim3(CND / 128, NTOK / 128), 256, GEMM_SMEM_H>>>(sln, aw1, ab1, t1,
        NTOK, CND, CND, nullptr, nullptr, 0);
    gemm_fp16<0><<<dim3(MODW / 128, NTOK / 128), 256, GEMM_SMEM_H>>>(t1, aw2, ab2, mod,
        NTOK, MODW, CND, nullptr, nullptr, 0);

    // edge bias (writes into scores buffer)
    edge_bias_mma<<<(CB * CL * CL) / 128, 128>>>(p_in, eln_w, eln_b, ew, eb, scores);

    // attention branch
    ln_mod1024<<<NTOK, 256>>>(h_in, mod, /*scale*/CD, /*shift*/0, x);
    gemm_fp16<0><<<dim3(3 * CD / 128, NTOK / 128), 256, GEMM_SMEM_H>>>(x, in_w, in_b, qkv,
        NTOK, 3 * CD, CD, nullptr, nullptr, 0);
    score_mma<<<dim3(4, 4, CB * CH), 256>>>(qkv, scores);
    attnv_mma<<<dim3(4, CB * CH), 256>>>(scores, qkv, o);
    gemm_fp16<2><<<dim3(CD / 128, NTOK / 128), 256, GEMM_SMEM_H>>>(o, out_w, out_b, h2,
        NTOK, CD, CD, h_in, mod, 2 * CD);

    // gated MLP branch
    ln_mod1024<<<NTOK, 256>>>(h2, mod, /*scale*/4 * CD, /*shift*/3 * CD, x);
    gemm_fp16<1><<<dim3(CMLP / 128, NTOK / 128), 256, GEMM_SMEM_H>>>(x, mw1, mb1, t2,
        NTOK, CMLP, CD, nullptr, nullptr, 0);
    gemm_fp16<2><<<dim3(CD / 128, NTOK / 128), 256, GEMM_SMEM_H>>>(t2, mw2, mb2, out,
        NTOK, CD, CMLP, h2, mod, 5 * CD);
}

// round 8
// speedup vs baseline: 1.0978x; 1.0469x over previous
#include <cuda_runtime.h>
#include <cuda_fp16.h>
#include <math.h>
#include <stdint.h>

// Problem constants
#define CB   4
#define CL   512
#define CD   1024
#define CND  512
#define CED  64
#define CH   16
#define CMLP 2048
#define CDH  64
#define NTOK (CB*CL)        // 2048
#define MODW (6*CD)         // 6144
#define EPSF 1e-5f

// ---------------- scratch ----------------
__device__ float g_sln[NTOK*CND];
__device__ float g_t1[NTOK*CND];
__device__ float g_mod[NTOK*MODW];
__device__ float g_scores[(size_t)CB*CH*CL*CL];   // holds edge bias only
__device__ float g_x[NTOK*CD];
__device__ float g_qkv[NTOK*3*CD];
__device__ float g_o[NTOK*CD];
__device__ float g_h2[NTOK*CD];
__device__ float g_t2[NTOK*CMLP];

// ---------------- utils ----------------
__device__ __forceinline__ float warp_sum(float v) {
#pragma unroll
    for (int o = 16; o > 0; o >>= 1) v += __shfl_xor_sync(0xffffffffu, v, o);
    return v;
}
__device__ __forceinline__ void mma_tf32(float c[4], const uint32_t a[4], const uint32_t b[2]) {
    asm volatile(
        "mma.sync.aligned.m16n8k8.row.col.f32.tf32.tf32.f32 "
        "{%0,%1,%2,%3}, {%4,%5,%6,%7}, {%8,%9}, {%0,%1,%2,%3};"
        : "+f"(c[0]), "+f"(c[1]), "+f"(c[2]), "+f"(c[3])
        : "r"(a[0]), "r"(a[1]), "r"(a[2]), "r"(a[3]), "r"(b[0]), "r"(b[1]));
}
__device__ __forceinline__ void mma_fp16(float c[4], const uint32_t a[4], const uint32_t b[2]) {
    asm volatile(
        "mma.sync.aligned.m16n8k16.row.col.f32.f16.f16.f32 "
        "{%0,%1,%2,%3}, {%4,%5,%6,%7}, {%8,%9}, {%0,%1,%2,%3};"
        : "+f"(c[0]), "+f"(c[1]), "+f"(c[2]), "+f"(c[3])
        : "r"(a[0]), "r"(a[1]), "r"(a[2]), "r"(a[3]), "r"(b[0]), "r"(b[1]));
}
__device__ __forceinline__ uint32_t pack_h2(float lo, float hi) {
    __half2 h = __floats2half2_rn(lo, hi);
    return *(uint32_t*)&h;
}

// ---------------- LN(s)*w+b, width 512 ----------------
__global__ void __launch_bounds__(128) ln_affine512(
    const float* __restrict__ x, const float* __restrict__ w,
    const float* __restrict__ b, float* __restrict__ out)
{
    int row = blockIdx.x;
    const float4* xr = (const float4*)(x + (size_t)row * CND);
    float4 v = xr[threadIdx.x];
    float s  = v.x + v.y + v.z + v.w;
    float ss = v.x*v.x + v.y*v.y + v.z*v.z + v.w*v.w;
    s = warp_sum(s); ss = warp_sum(ss);
    __shared__ float sh[8];
    int wid = threadIdx.x >> 5, lid = threadIdx.x & 31;
    if (lid == 0) { sh[wid] = s; sh[4 + wid] = ss; }
    __syncthreads();
    s  = sh[0] + sh[1] + sh[2] + sh[3];
    ss = sh[4] + sh[5] + sh[6] + sh[7];
    float mean = s * (1.0f / CND);
    float var  = ss * (1.0f / CND) - mean * mean;
    float rinv = rsqrtf(var + EPSF);
    int d = threadIdx.x * 4;
    float4 wv = *(const float4*)(w + d);
    float4 bv = *(const float4*)(b + d);
    float4 o;
    o.x = (v.x - mean) * rinv * wv.x + bv.x;
    o.y = (v.y - mean) * rinv * wv.y + bv.y;
    o.z = (v.z - mean) * rinv * wv.z + bv.z;
    o.w = (v.w - mean) * rinv * wv.w + bv.w;
    ((float4*)(out + (size_t)row * CND))[threadIdx.x] = o;
}

// ---------------- LN(h)*(1+scale)+shift, width 1024 ----------------
__global__ void __launch_bounds__(256) ln_mod1024(
    const float* __restrict__ x, const float* __restrict__ mod,
    int scale_off, int shift_off, float* __restrict__ out)
{
    int row = blockIdx.x;
    float4 v = ((const float4*)(x + (size_t)row * CD))[threadIdx.x];
    float s  = v.x + v.y + v.z + v.w;
    float ss = v.x*v.x + v.y*v.y + v.z*v.z + v.w*v.w;
    s = warp_sum(s); ss = warp_sum(ss);
    __shared__ float sh[16];
    int wid = threadIdx.x >> 5, lid = threadIdx.x & 31;
    if (lid == 0) { sh[wid] = s; sh[8 + wid] = ss; }
    __syncthreads();
    s = 0.f; ss = 0.f;
#pragma unroll
    for (int i = 0; i < 8; i++) { s += sh[i]; ss += sh[8 + i]; }
    float mean = s * (1.0f / CD);
    float var  = ss * (1.0f / CD) - mean * mean;
    float rinv = rsqrtf(var + EPSF);
    int d = threadIdx.x * 4;
    const float* mrow = mod + (size_t)row * MODW;
    float4 sc = *(const float4*)(mrow + scale_off + d);
    float4 sf = *(const float4*)(mrow + shift_off + d);
    float4 o;
    o.x = ((v.x - mean) * rinv) * (1.0f + sc.x) + sf.x;
    o.y = ((v.y - mean) * rinv) * (1.0f + sc.y) + sf.y;
    o.z = ((v.z - mean) * rinv) * (1.0f + sc.z) + sf.z;
    o.w = ((v.w - mean) * rinv) * (1.0f + sc.w) + sf.w;
    ((float4*)(out + (size_t)row * CD))[threadIdx.x] = o;
}

// ---------------- fp16 NT GEMM (m16n8k16, fp32 accum) ----------------
#define GEMM_SMEM_H (2 * 2 * 128 * 20 * 4)
template<int EPI>
__global__ void __launch_bounds__(256, 2) gemm_fp16(
    const float* __restrict__ A, const float* __restrict__ W,
    const float* __restrict__ bias, float* __restrict__ C,
    int M, int N, int K,
    const float* __restrict__ res, const float* __restrict__ gate, int gate_off)
{
    extern __shared__ uint32_t dynh[];
    uint32_t* As = dynh;                    // [2][128][20]
    uint32_t* Ws = dynh + 2 * 128 * 20;     // [2][128][20]

    int bm = blockIdx.y * 128;
    int bn = blockIdx.x * 128;
    int tid  = threadIdx.x;
    int warp = tid >> 5, lane = tid & 31;
    int g = lane >> 2, t = lane & 3;
    int wm = (warp & 1) * 64;
    int wn = (warp >> 1) * 32;

    float acc[4][4][4];
#pragma unroll
    for (int i = 0; i < 4; i++)
#pragma unroll
        for (int j = 0; j < 4; j++)
#pragma unroll
            for (int q = 0; q < 4; q++) acc[i][j][q] = 0.f;

    int ldr = tid >> 3;
    int kv  = (tid & 7) * 4;
    int jp  = kv >> 1;

    float4 ra[4], rw[4];
#pragma unroll
    for (int r = 0; r < 4; r++) {
        int row = ldr + r * 32;
        ra[r] = *(const float4*)(A + (size_t)(bm + row) * K + kv);
        rw[r] = *(const float4*)(W + (size_t)(bn + row) * K + kv);
    }
#pragma unroll
    for (int r = 0; r < 4; r++) {
        int row = ldr + r * 32;
        uint2 ua; ua.x = pack_h2(ra[r].x, ra[r].y); ua.y = pack_h2(ra[r].z, ra[r].w);
        *(uint2*)&As[(size_t)row * 20 + jp] = ua;
        uint2 uw; uw.x = pack_h2(rw[r].x, rw[r].y); uw.y = pack_h2(rw[r].z, rw[r].w);
        *(uint2*)&Ws[(size_t)row * 20 + jp] = uw;
    }
    __syncthreads();

    int nIter = K >> 5;
    for (int it = 0; it < nIter; ++it) {
        if (it + 1 < nIter) {
            int k0n = (it + 1) << 5;
#pragma unroll
            for (int r = 0; r < 4; r++) {
                int row = ldr + r * 32;
                ra[r] = *(const float4*)(A + (size_t)(bm + row) * K + k0n + kv);
                rw[r] = *(const float4*)(W + (size_t)(bn + row) * K + k0n + kv);
            }
        }
        int st = it & 1;
        const uint32_t* Ab = As + (size_t)st * 128 * 20;
        const uint32_t* Wb = Ws + (size_t)st * 128 * 20;
#pragma unroll
        for (int ks = 0; ks < 2; ks++) {
            int kp = ks * 8;
            uint32_t af[4][4];
#pragma unroll
            for (int mt = 0; mt < 4; mt++) {
                int r0 = wm + mt * 16 + g;
                af[mt][0] = Ab[(size_t)r0 * 20 + kp + t];
                af[mt][1] = Ab[(size_t)(r0 + 8) * 20 + kp + t];
                af[mt][2] = Ab[(size_t)r0 * 20 + kp + t + 4];
                af[mt][3] = Ab[(size_t)(r0 + 8) * 20 + kp + t + 4];
            }
            uint32_t bf[4][2];
#pragma unroll
            for (int nt = 0; nt < 4; nt++) {
                int c0 = wn + nt * 8 + g;
                bf[nt][0] = Wb[(size_t)c0 * 20 + kp + t];
                bf[nt][1] = Wb[(size_t)c0 * 20 + kp + t + 4];
            }
#pragma unroll
            for (int mt = 0; mt < 4; mt++)
#pragma unroll
                for (int nt = 0; nt < 4; nt++)
                    mma_fp16(acc[mt][nt], af[mt], bf[nt]);
        }
        __syncthreads();
        if (it + 1 < nIter) {
            int stn = (it + 1) & 1;
            uint32_t* An = As + (size_t)stn * 128 * 20;
            uint32_t* Wn = Ws + (size_t)stn * 128 * 20;
#pragma unroll
            for (int r = 0; r < 4; r++) {
                int row = ldr + r * 32;
                uint2 ua; ua.x = pack_h2(ra[r].x, ra[r].y); ua.y = pack_h2(ra[r].z, ra[r].w);
                *(uint2*)&An[(size_t)row * 20 + jp] = ua;
                uint2 uw; uw.x = pack_h2(rw[r].x, rw[r].y); uw.y = pack_h2(rw[r].z, rw[r].w);
                *(uint2*)&Wn[(size_t)row * 20 + jp] = uw;
            }
            __syncthreads();
        }
    }

#pragma unroll
    for (int mt = 0; mt < 4; mt++) {
#pragma unroll
        for (int half = 0; half < 2; half++) {
            int row = bm + wm + mt * 16 + g + half * 8;
            float* cr = C + (size_t)row * N;
            const float* rr = (EPI == 2) ? res + (size_t)row * N : nullptr;
            const float* gr = (EPI == 2) ? gate + (size_t)row * MODW + gate_off : nullptr;
#pragma unroll
            for (int nt = 0; nt < 4; nt++) {
                int col = bn + wn + nt * 8 + 2 * t;
                float v0 = acc[mt][nt][half * 2 + 0] + bias[col];
                float v1 = acc[mt][nt][half * 2 + 1] + bias[col + 1];
                if (EPI == 1) {
                    v0 = v0 / (1.0f + expf(-v0));
                    v1 = v1 / (1.0f + expf(-v1));
                }
                if (EPI == 2) {
                    v0 = rr[col]     + v0 * gr[col];
                    v1 = rr[col + 1] + v1 * gr[col + 1];
                }
                float2 o2; o2.x = v0; o2.y = v1;
                *(float2*)(cr + col) = o2;
            }
        }
    }
}

// ---------------- edge bias: LN folded into GEMM epilogue, tf32 MMA ----------------
__global__ void __launch_bounds__(128) edge_bias_mma(
    const float* __restrict__ p, const float* __restrict__ lnw, const float* __restrict__ lnb,
    const float* __restrict__ ew, const float* __restrict__ eb, float* __restrict__ bias)
{
    __shared__ float rows[128][68];
    __shared__ float W2T[16][68];
    __shared__ float meanv[128], rinvv[128], c1s[16], c2s[16];
    int tid = threadIdx.x;
    size_t base = (size_t)blockIdx.x * 128;

#pragma unroll
    for (int r = 0; r < 16; r++) {
        int id  = tid + r * 128;
        int row = id >> 4;
        int c4  = (id & 15) * 4;
        *(float4*)&rows[row][c4] = *(const float4*)(p + (base + row) * 64 + c4);
    }
    for (int i = tid; i < 1024; i += 128) {
        int h = i >> 6, k = i & 63;
        W2T[h][k] = ew[i] * lnw[k];
    }
    if (tid < 16) {
        float a = 0.f, b2 = 0.f;
        for (int k = 0; k < 64; k++) {
            float e = ew[tid * 64 + k];
            a  += lnw[k] * e;
            b2 += lnb[k] * e;
        }
        c1s[tid] = a;
        c2s[tid] = b2 + eb[tid];
    }
    __syncthreads();

    {
        float s = 0.f, ss = 0.f;
#pragma unroll
        for (int q = 0; q < 16; q++) {
            float4 x = *(const float4*)&rows[tid][q * 4];
            s  += x.x + x.y + x.z + x.w;
            ss += x.x*x.x + x.y*x.y + x.z*x.z + x.w*x.w;
        }
        float mean = s * (1.0f / 64.0f);
        float var  = ss * (1.0f / 64.0f) - mean * mean;
        meanv[tid] = mean;
        rinvv[tid] = rsqrtf(var + EPSF);
    }
    __syncthreads();

    int warp = tid >> 5, lane = tid & 31;
    int g = lane >> 2, t = lane & 3;
    float acc[2][2][4];
#pragma unroll
    for (int i = 0; i < 2; i++)
#pragma unroll
        for (int j = 0; j < 2; j++)
#pragma unroll
            for (int q = 0; q < 4; q++) acc[i][j][q] = 0.f;

#pragma unroll
    for (int ks = 0; ks < 8; ks++) {
        int kk = ks * 8;
        uint32_t af[2][4];
#pragma unroll
        for (int mt = 0; mt < 2; mt++) {
            int r0 = warp * 32 + mt * 16 + g;
            af[mt][0] = __float_as_uint(rows[r0][kk + t]);
            af[mt][1] = __float_as_uint(rows[r0 + 8][kk + t]);
            af[mt][2] = __float_as_uint(rows[r0][kk + t + 4]);
            af[mt][3] = __float_as_uint(rows[r0 + 8][kk + t + 4]);
        }
        uint32_t bf[2][2];
#pragma unroll
        for (int nt = 0; nt < 2; nt++) {
            int c0 = nt * 8 + g;
            bf[nt][0] = __float_as_uint(W2T[c0][kk + t]);
            bf[nt][1] = __float_as_uint(W2T[c0][kk + t + 4]);
        }
#pragma unroll
        for (int mt = 0; mt < 2; mt++)
#pragma unroll
            for (int nt = 0; nt < 2; nt++)
                mma_tf32(acc[mt][nt], af[mt], bf[nt]);
    }

    int b  = (int)(base >> 18);
    int ij = (int)(base & 262143);
    int i  = ij >> 9;
    int j0 = ij & 511;
    float* bb = bias + (((size_t)b * 16) * 512 + i) * 512 + j0;
#pragma unroll
    for (int mt = 0; mt < 2; mt++) {
#pragma unroll
        for (int half = 0; half < 2; half++) {
            int rl = warp * 32 + mt * 16 + g + half * 8;
            float m  = meanv[rl];
            float rv = rinvv[rl];
#pragma unroll
            for (int nt = 0; nt < 2; nt++) {
#pragma unroll
                for (int c = 0; c < 2; c++) {
                    int h = nt * 8 + 2 * t + c;
                    bb[(size_t)h * 512 * 512 + rl] =
                        rv * (acc[mt][nt][half * 2 + c] - m * c1s[h]) + c2s[h];
                }
            }
        }
    }
}

// ---------------- fused flash attention: S=QK^T/8+bias, online softmax, O=P@V ----------------
// grid (4 i-tiles, 64 bh), 256 threads (8 warps x 16 rows).
// smem: Qs[128][68] | Ks[64][68] | Vs[64][68] | Ps[128][68]  (floats)
#define FL_SMEM ((128*68 + 64*68 + 64*68 + 128*68) * 4)
__global__ void __launch_bounds__(256) flash_attn(
    const float* __restrict__ bias, const float* __restrict__ qkv, float* __restrict__ o)
{
    extern __shared__ float fsm[];
    float* Qs = fsm;                    // [128][68]
    float* Ks = Qs + 128 * 68;          // [64][68]
    float* Vs = Ks + 64 * 68;           // [64][68]
    float* Ps = Vs + 64 * 68;           // [128][68]

    int bh = blockIdx.y; int b = bh >> 4, h = bh & 15;
    int i0 = blockIdx.x * 128;
    int tid  = threadIdx.x;
    int warp = tid >> 5, lane = tid & 31;
    int g = lane >> 2, t = lane & 3;
    int r0 = warp * 16 + g;          // warp-local rows r0, r0+8

    const float* qb = qkv + (size_t)(b * CL) * (3 * CD) + h * CDH;
    const float* kb = qb + CD;
    const float* vb = qb + 2 * CD;
    const float* bbase = bias + ((size_t)bh * CL + i0) * CL;

    // load Q tile [128][64]
#pragma unroll
    for (int r = 0; r < 8; r++) {
        int id  = tid + r * 256;
        int row = id >> 4;
        int c4  = (id & 15) * 4;
        *(float4*)&Qs[row * 68 + c4] = *(const float4*)(qb + (size_t)(i0 + row) * (3 * CD) + c4);
    }

    float Oa[8][4];
#pragma unroll
    for (int nt = 0; nt < 8; nt++)
#pragma unroll
        for (int q = 0; q < 4; q++) Oa[nt][q] = 0.f;
    float m0 = -1e30f, m1 = -1e30f, l0 = 0.f, l1 = 0.f;

    for (int j0 = 0; j0 < CL; j0 += 64) {
        __syncthreads();   // protect Ks/Vs from previous iteration readers
        // load K,V tiles [64][64]
#pragma unroll
        for (int r = 0; r < 4; r++) {
            int id  = tid + r * 256;
            int row = id >> 4;
            int c4  = (id & 15) * 4;
            *(float4*)&Ks[row * 68 + c4] = *(const float4*)(kb + (size_t)(j0 + row) * (3 * CD) + c4);
            *(float4*)&Vs[row * 68 + c4] = *(const float4*)(vb + (size_t)(j0 + row) * (3 * CD) + c4);
        }
        __syncthreads();

        // S = Q K^T (tf32), 16 rows x 64 cols per warp
        float sa[8][4];
#pragma unroll
        for (int nt = 0; nt < 8; nt++)
#pragma unroll
            for (int q = 0; q < 4; q++) sa[nt][q] = 0.f;
#pragma unroll
        for (int ks = 0; ks < 8; ks++) {
            int kk = ks * 8;
            uint32_t af[4];
            af[0] = __float_as_uint(Qs[r0 * 68 + kk + t]);
            af[1] = __float_as_uint(Qs[(r0 + 8) * 68 + kk + t]);
            af[2] = __float_as_uint(Qs[r0 * 68 + kk + t + 4]);
            af[3] = __float_as_uint(Qs[(r0 + 8) * 68 + kk + t + 4]);
#pragma unroll
            for (int nt = 0; nt < 8; nt++) {
                int c0 = nt * 8 + g;
                uint32_t bf[2];
                bf[0] = __float_as_uint(Ks[c0 * 68 + kk + t]);
                bf[1] = __float_as_uint(Ks[c0 * 68 + kk + t + 4]);
                mma_tf32(sa[nt], af, bf);
            }
        }

        // finish S: *1/8 + bias; track row maxima
        float mt0 = -1e30f, mt1 = -1e30f;
#pragma unroll
        for (int nt = 0; nt < 8; nt++) {
            int col = j0 + nt * 8 + 2 * t;
            float2 b0 = *(const float2*)(bbase + (size_t)r0 * CL + col);
            float2 b1 = *(const float2*)(bbase + (size_t)(r0 + 8) * CL + col);
            sa[nt][0] = fmaf(sa[nt][0], 0.125f, b0.x);
            sa[nt][1] = fmaf(sa[nt][1], 0.125f, b0.y);
            sa[nt][2] = fmaf(sa[nt][2], 0.125f, b1.x);
            sa[nt][3] = fmaf(sa[nt][3], 0.125f, b1.y);
            mt0 = fmaxf(mt0, fmaxf(sa[nt][0], sa[nt][1]));
            mt1 = fmaxf(mt1, fmaxf(sa[nt][2], sa[nt][3]));
        }
        // reduce across quad (t lanes share row)
#pragma unroll
        for (int x = 1; x <= 2; x <<= 1) {
            mt0 = fmaxf(mt0, __shfl_xor_sync(0xffffffffu, mt0, x));
            mt1 = fmaxf(mt1, __shfl_xor_sync(0xffffffffu, mt1, x));
        }
        float mn0 = fmaxf(m0, mt0), mn1 = fmaxf(m1, mt1);
        float sc0 = __expf(m0 - mn0), sc1 = __expf(m1 - mn1);
        m0 = mn0; m1 = mn1;

        // P = exp(S - m), row sums, write P to smem (warp-private rows)
        float ps0 = 0.f, ps1 = 0.f;
#pragma unroll
        for (int nt = 0; nt < 8; nt++) {
            int jl = nt * 8 + 2 * t;
            float p00 = __expf(sa[nt][0] - m0);
            float p01 = __expf(sa[nt][1] - m0);
            float p10 = __expf(sa[nt][2] - m1);
            float p11 = __expf(sa[nt][3] - m1);
            ps0 += p00 + p01; ps1 += p10 + p11;
            float2 w0; w0.x = p00; w0.y = p01;
            float2 w1; w1.x = p10; w1.y = p11;
            *(float2*)&Ps[r0 * 68 + jl] = w0;
            *(float2*)&Ps[(r0 + 8) * 68 + jl] = w1;
        }
#pragma unroll
        for (int x = 1; x <= 2; x <<= 1) {
            ps0 += __shfl_xor_sync(0xffffffffu, ps0, x);
            ps1 += __shfl_xor_sync(0xffffffffu, ps1, x);
        }
        l0 = l0 * sc0 + ps0;
        l1 = l1 * sc1 + ps1;

        // rescale O
#pragma unroll
        for (int nt = 0; nt < 8; nt++) {
            Oa[nt][0] *= sc0; Oa[nt][1] *= sc0;
            Oa[nt][2] *= sc1; Oa[nt][3] *= sc1;
        }
        __syncwarp();   // P rows are warp-private

        // O += P @ V (tf32, NN: B from Vs[k][n])
#pragma unroll
        for (int ks = 0; ks < 8; ks++) {
            int kk = ks * 8;
            uint32_t af[4];
            af[0] = __float_as_uint(Ps[r0 * 68 + kk + t]);
            af[1] = __float_as_uint(Ps[(r0 + 8) * 68 + kk + t]);
            af[2] = __float_as_uint(Ps[r0 * 68 + kk + t + 4]);
            af[3] = __float_as_uint(Ps[(r0 + 8) * 68 + kk + t + 4]);
#pragma unroll
            for (int nt = 0; nt < 8; nt++) {
                int c0 = nt * 8 + g;
                uint32_t bf[2];
                bf[0] = __float_as_uint(Vs[(kk + t) * 68 + c0]);
                bf[1] = __float_as_uint(Vs[(kk + t + 4) * 68 + c0]);
                mma_tf32(Oa[nt], af, bf);
            }
        }
    }

    // epilogue: normalize and store
    float il0 = 1.0f / l0, il1 = 1.0f / l1;
    float* o0 = o + (size_t)(b * CL + i0 + r0) * CD + h * CDH;
    float* o1 = o + (size_t)(b * CL + i0 + r0 + 8) * CD + h * CDH;
#pragma unroll
    for (int nt = 0; nt < 8; nt++) {
        int d = nt * 8 + 2 * t;
        float2 w0; w0.x = Oa[nt][0] * il0; w0.y = Oa[nt][1] * il0;
        float2 w1; w1.x = Oa[nt][2] * il1; w1.y = Oa[nt][3] * il1;
        *(float2*)(o0 + d) = w0;
        *(float2*)(o1 + d) = w1;
    }
}

// ---------------- launch ----------------
extern "C" void kernel_launch(void* const* d_in, const int* in_sizes, int n_in,
                              void* d_out, int out_size)
{
    const float* h_in  = (const float*)d_in[0];
    const float* s_in  = (const float*)d_in[1];
    const float* p_in  = (const float*)d_in[2];
    const float* aln_w = (const float*)d_in[3];
    const float* aln_b = (const float*)d_in[4];
    const float* aw1   = (const float*)d_in[5];
    const float* ab1   = (const float*)d_in[6];
    const float* aw2   = (const float*)d_in[7];
    const float* ab2   = (const float*)d_in[8];
    const float* eln_w = (const float*)d_in[9];
    const float* eln_b = (const float*)d_in[10];
    const float* ew    = (const float*)d_in[11];
    const float* eb    = (const float*)d_in[12];
    const float* in_w  = (const float*)d_in[13];
    const float* in_b  = (const float*)d_in[14];
    const float* out_w = (const float*)d_in[15];
    const float* out_b = (const float*)d_in[16];
    const float* mw1   = (const float*)d_in[17];
    const float* mb1   = (const float*)d_in[18];
    const float* mw2   = (const float*)d_in[19];
    const float* mb2   = (const float*)d_in[20];
    float* out = (float*)d_out;

    float *sln, *t1, *mod, *scores, *x, *qkv, *o, *h2, *t2;
    cudaGetSymbolAddress((void**)&sln,    g_sln);
    cudaGetSymbolAddress((void**)&t1,     g_t1);
    cudaGetSymbolAddress((void**)&mod,    g_mod);
    cudaGetSymbolAddress((void**)&scores, g_scores);
    cudaGetSymbolAddress((void**)&x,      g_x);
    cudaGetSymbolAddress((void**)&qkv,    g_qkv);
    cudaGetSymbolAddress((void**)&o,      g_o);
    cudaGetSymbolAddress((void**)&h2,     g_h2);
    cudaGetSymbolAddress((void**)&t2,     g_t2);

    cudaFuncSetAttribute(gemm_fp16<0>, cudaFuncAttributeMaxDynamicSharedMemorySize, GEMM_SMEM_H);
    cudaFuncSetAttribute(gemm_fp16<1>, cudaFuncAttributeMaxDynamicSharedMemorySize, GEMM_SMEM_H);
    cudaFuncSetAttribute(gemm_fp16<2>, cudaFuncAttributeMaxDynamicSharedMemorySize, GEMM_SMEM_H);
    cudaFuncSetAttribute(flash_attn,   cudaFuncAttributeMaxDynamicSharedMemorySize, FL_SMEM);

    // adaLN modulation chain
    ln_affine512<<<NTOK, 128>>>(s_in, aln_w, aln_b, sln);
    gemm_fp16<1><<<dim3(CND / 128, NTOK / 128), 256, GEMM_SMEM_H>>>(sln, aw1, ab1, t1,
        NTOK, CND, CND, nullptr, nullptr, 0);
    gemm_fp16<0><<<dim3(MODW / 128, NTOK / 128), 256, GEMM_SMEM_H>>>(t1, aw2, ab2, mod,
        NTOK, MODW, CND, nullptr, nullptr, 0);

    // edge bias (writes into scores buffer)
    edge_bias_mma<<<(CB * CL * CL) / 128, 128>>>(p_in, eln_w, eln_b, ew, eb, scores);

    // attention branch
    ln_mod1024<<<NTOK, 256>>>(h_in, mod, /*scale*/CD, /*shift*/0, x);
    gemm_fp16<0><<<dim3(3 * CD / 128, NTOK / 128), 256, GEMM_SMEM_H>>>(x, in_w, in_b, qkv,
        NTOK, 3 * CD, CD, nullptr, nullptr, 0);
    flash_attn<<<dim3(CL / 128, CB * CH), 256, FL_SMEM>>>(scores, qkv, o);
    gemm_fp16<2><<<dim3(CD / 128, NTOK / 128), 256, GEMM_SMEM_H>>>(o, out_w, out_b, h2,
        NTOK, CD, CD, h_in, mod, 2 * CD);

    // gated MLP branch
    ln_mod1024<<<NTOK, 256>>>(h2, mod, /*scale*/4 * CD, /*shift*/3 * CD, x);
    gemm_fp16<1><<<dim3(CMLP / 128, NTOK / 128), 256, GEMM_SMEM_H>>>(x, mw1, mb1, t2,
        NTOK, CMLP, CD, nullptr, nullptr, 0);
    gemm_fp16<2><<<dim3(CD / 128, NTOK / 128), 256, GEMM_SMEM_H>>>(t2, mw2, mb2, out,
        NTOK, CD, CMLP, h2, mod, 5 * CD);
}

// round 9
// speedup vs baseline: 1.1147x; 1.0154x over previous
#include <cuda_runtime.h>
#include <cuda_fp16.h>
#include <math.h>
#include <stdint.h>

// Problem constants
#define CB   4
#define CL   512
#define CD   1024
#define CND  512
#define CED  64
#define CH   16
#define CMLP 2048
#define CDH  64
#define NTOK (CB*CL)        // 2048
#define MODW (6*CD)         // 6144
#define EPSF 1e-5f

// ---------------- scratch ----------------
__device__ float g_sln[NTOK*CND];
__device__ float g_t1[NTOK*CND];
__device__ float g_mod[NTOK*MODW];
__device__ __half g_bias[(size_t)CB*CH*CL*CL];   // edge bias, fp16
__device__ float g_x[NTOK*CD];
__device__ float g_qkv[NTOK*3*CD];
__device__ float g_o[NTOK*CD];
__device__ float g_h2[NTOK*CD];
__device__ float g_t2[NTOK*CMLP];

// ---------------- utils ----------------
__device__ __forceinline__ float warp_sum(float v) {
#pragma unroll
    for (int o = 16; o > 0; o >>= 1) v += __shfl_xor_sync(0xffffffffu, v, o);
    return v;
}
__device__ __forceinline__ void mma_tf32(float c[4], const uint32_t a[4], const uint32_t b[2]) {
    asm volatile(
        "mma.sync.aligned.m16n8k8.row.col.f32.tf32.tf32.f32 "
        "{%0,%1,%2,%3}, {%4,%5,%6,%7}, {%8,%9}, {%0,%1,%2,%3};"
        : "+f"(c[0]), "+f"(c[1]), "+f"(c[2]), "+f"(c[3])
        : "r"(a[0]), "r"(a[1]), "r"(a[2]), "r"(a[3]), "r"(b[0]), "r"(b[1]));
}
__device__ __forceinline__ void mma_fp16(float c[4], const uint32_t a[4], const uint32_t b[2]) {
    asm volatile(
        "mma.sync.aligned.m16n8k16.row.col.f32.f16.f16.f32 "
        "{%0,%1,%2,%3}, {%4,%5,%6,%7}, {%8,%9}, {%0,%1,%2,%3};"
        : "+f"(c[0]), "+f"(c[1]), "+f"(c[2]), "+f"(c[3])
        : "r"(a[0]), "r"(a[1]), "r"(a[2]), "r"(a[3]), "r"(b[0]), "r"(b[1]));
}
__device__ __forceinline__ uint32_t pack_h2(float lo, float hi) {
    __half2 h = __floats2half2_rn(lo, hi);
    return *(uint32_t*)&h;
}

// ---------------- LN(s)*w+b, width 512 ----------------
__global__ void __launch_bounds__(128) ln_affine512(
    const float* __restrict__ x, const float* __restrict__ w,
    const float* __restrict__ b, float* __restrict__ out)
{
    int row = blockIdx.x;
    const float4* xr = (const float4*)(x + (size_t)row * CND);
    float4 v = xr[threadIdx.x];
    float s  = v.x + v.y + v.z + v.w;
    float ss = v.x*v.x + v.y*v.y + v.z*v.z + v.w*v.w;
    s = warp_sum(s); ss = warp_sum(ss);
    __shared__ float sh[8];
    int wid = threadIdx.x >> 5, lid = threadIdx.x & 31;
    if (lid == 0) { sh[wid] = s; sh[4 + wid] = ss; }
    __syncthreads();
    s  = sh[0] + sh[1] + sh[2] + sh[3];
    ss = sh[4] + sh[5] + sh[6] + sh[7];
    float mean = s * (1.0f / CND);
    float var  = ss * (1.0f / CND) - mean * mean;
    float rinv = rsqrtf(var + EPSF);
    int d = threadIdx.x * 4;
    float4 wv = *(const float4*)(w + d);
    float4 bv = *(const float4*)(b + d);
    float4 o;
    o.x = (v.x - mean) * rinv * wv.x + bv.x;
    o.y = (v.y - mean) * rinv * wv.y + bv.y;
    o.z = (v.z - mean) * rinv * wv.z + bv.z;
    o.w = (v.w - mean) * rinv * wv.w + bv.w;
    ((float4*)(out + (size_t)row * CND))[threadIdx.x] = o;
}

// ---------------- LN(h)*(1+scale)+shift, width 1024 ----------------
__global__ void __launch_bounds__(256) ln_mod1024(
    const float* __restrict__ x, const float* __restrict__ mod,
    int scale_off, int shift_off, float* __restrict__ out)
{
    int row = blockIdx.x;
    float4 v = ((const float4*)(x + (size_t)row * CD))[threadIdx.x];
    float s  = v.x + v.y + v.z + v.w;
    float ss = v.x*v.x + v.y*v.y + v.z*v.z + v.w*v.w;
    s = warp_sum(s); ss = warp_sum(ss);
    __shared__ float sh[16];
    int wid = threadIdx.x >> 5, lid = threadIdx.x & 31;
    if (lid == 0) { sh[wid] = s; sh[8 + wid] = ss; }
    __syncthreads();
    s = 0.f; ss = 0.f;
#pragma unroll
    for (int i = 0; i < 8; i++) { s += sh[i]; ss += sh[8 + i]; }
    float mean = s * (1.0f / CD);
    float var  = ss * (1.0f / CD) - mean * mean;
    float rinv = rsqrtf(var + EPSF);
    int d = threadIdx.x * 4;
    const float* mrow = mod + (size_t)row * MODW;
    float4 sc = *(const float4*)(mrow + scale_off + d);
    float4 sf = *(const float4*)(mrow + shift_off + d);
    float4 o;
    o.x = ((v.x - mean) * rinv) * (1.0f + sc.x) + sf.x;
    o.y = ((v.y - mean) * rinv) * (1.0f + sc.y) + sf.y;
    o.z = ((v.z - mean) * rinv) * (1.0f + sc.z) + sf.z;
    o.w = ((v.w - mean) * rinv) * (1.0f + sc.w) + sf.w;
    ((float4*)(out + (size_t)row * CD))[threadIdx.x] = o;
}

// ---------------- fp16 NT GEMM (m16n8k16, fp32 accum) ----------------
#define GEMM_SMEM_H (2 * 2 * 128 * 20 * 4)
template<int EPI>
__global__ void __launch_bounds__(256, 2) gemm_fp16(
    const float* __restrict__ A, const float* __restrict__ W,
    const float* __restrict__ bias, float* __restrict__ C,
    int M, int N, int K,
    const float* __restrict__ res, const float* __restrict__ gate, int gate_off)
{
    extern __shared__ uint32_t dynh[];
    uint32_t* As = dynh;                    // [2][128][20]
    uint32_t* Ws = dynh + 2 * 128 * 20;     // [2][128][20]

    int bm = blockIdx.y * 128;
    int bn = blockIdx.x * 128;
    int tid  = threadIdx.x;
    int warp = tid >> 5, lane = tid & 31;
    int g = lane >> 2, t = lane & 3;
    int wm = (warp & 1) * 64;
    int wn = (warp >> 1) * 32;

    float acc[4][4][4];
#pragma unroll
    for (int i = 0; i < 4; i++)
#pragma unroll
        for (int j = 0; j < 4; j++)
#pragma unroll
            for (int q = 0; q < 4; q++) acc[i][j][q] = 0.f;

    int ldr = tid >> 3;
    int kv  = (tid & 7) * 4;
    int jp  = kv >> 1;

    float4 ra[4], rw[4];
#pragma unroll
    for (int r = 0; r < 4; r++) {
        int row = ldr + r * 32;
        ra[r] = *(const float4*)(A + (size_t)(bm + row) * K + kv);
        rw[r] = *(const float4*)(W + (size_t)(bn + row) * K + kv);
    }
#pragma unroll
    for (int r = 0; r < 4; r++) {
        int row = ldr + r * 32;
        uint2 ua; ua.x = pack_h2(ra[r].x, ra[r].y); ua.y = pack_h2(ra[r].z, ra[r].w);
        *(uint2*)&As[(size_t)row * 20 + jp] = ua;
        uint2 uw; uw.x = pack_h2(rw[r].x, rw[r].y); uw.y = pack_h2(rw[r].z, rw[r].w);
        *(uint2*)&Ws[(size_t)row * 20 + jp] = uw;
    }
    __syncthreads();

    int nIter = K >> 5;
    for (int it = 0; it < nIter; ++it) {
        if (it + 1 < nIter) {
            int k0n = (it + 1) << 5;
#pragma unroll
            for (int r = 0; r < 4; r++) {
                int row = ldr + r * 32;
                ra[r] = *(const float4*)(A + (size_t)(bm + row) * K + k0n + kv);
                rw[r] = *(const float4*)(W + (size_t)(bn + row) * K + k0n + kv);
            }
        }
        int st = it & 1;
        const uint32_t* Ab = As + (size_t)st * 128 * 20;
        const uint32_t* Wb = Ws + (size_t)st * 128 * 20;
#pragma unroll
        for (int ks = 0; ks < 2; ks++) {
            int kp = ks * 8;
            uint32_t af[4][4];
#pragma unroll
            for (int mt = 0; mt < 4; mt++) {
                int r0 = wm + mt * 16 + g;
                af[mt][0] = Ab[(size_t)r0 * 20 + kp + t];
                af[mt][1] = Ab[(size_t)(r0 + 8) * 20 + kp + t];
                af[mt][2] = Ab[(size_t)r0 * 20 + kp + t + 4];
                af[mt][3] = Ab[(size_t)(r0 + 8) * 20 + kp + t + 4];
            }
            uint32_t bf[4][2];
#pragma unroll
            for (int nt = 0; nt < 4; nt++) {
                int c0 = wn + nt * 8 + g;
                bf[nt][0] = Wb[(size_t)c0 * 20 + kp + t];
                bf[nt][1] = Wb[(size_t)c0 * 20 + kp + t + 4];
            }
#pragma unroll
            for (int mt = 0; mt < 4; mt++)
#pragma unroll
                for (int nt = 0; nt < 4; nt++)
                    mma_fp16(acc[mt][nt], af[mt], bf[nt]);
        }
        __syncthreads();
        if (it + 1 < nIter) {
            int stn = (it + 1) & 1;
            uint32_t* An = As + (size_t)stn * 128 * 20;
            uint32_t* Wn = Ws + (size_t)stn * 128 * 20;
#pragma unroll
            for (int r = 0; r < 4; r++) {
                int row = ldr + r * 32;
                uint2 ua; ua.x = pack_h2(ra[r].x, ra[r].y); ua.y = pack_h2(ra[r].z, ra[r].w);
                *(uint2*)&An[(size_t)row * 20 + jp] = ua;
                uint2 uw; uw.x = pack_h2(rw[r].x, rw[r].y); uw.y = pack_h2(rw[r].z, rw[r].w);
                *(uint2*)&Wn[(size_t)row * 20 + jp] = uw;
            }
            __syncthreads();
        }
    }

#pragma unroll
    for (int mt = 0; mt < 4; mt++) {
#pragma unroll
        for (int half = 0; half < 2; half++) {
            int row = bm + wm + mt * 16 + g + half * 8;
            float* cr = C + (size_t)row * N;
            const float* rr = (EPI == 2) ? res + (size_t)row * N : nullptr;
            const float* gr = (EPI == 2) ? gate + (size_t)row * MODW + gate_off : nullptr;
#pragma unroll
            for (int nt = 0; nt < 4; nt++) {
                int col = bn + wn + nt * 8 + 2 * t;
                float v0 = acc[mt][nt][half * 2 + 0] + bias[col];
                float v1 = acc[mt][nt][half * 2 + 1] + bias[col + 1];
                if (EPI == 1) {
                    v0 = v0 / (1.0f + expf(-v0));
                    v1 = v1 / (1.0f + expf(-v1));
                }
                if (EPI == 2) {
                    v0 = rr[col]     + v0 * gr[col];
                    v1 = rr[col + 1] + v1 * gr[col + 1];
                }
                float2 o2; o2.x = v0; o2.y = v1;
                *(float2*)(cr + col) = o2;
            }
        }
    }
}

// ---------------- edge bias: LN folded into GEMM epilogue, tf32 MMA, fp16 out ----------------
__global__ void __launch_bounds__(128) edge_bias_mma(
    const float* __restrict__ p, const float* __restrict__ lnw, const float* __restrict__ lnb,
    const float* __restrict__ ew, const float* __restrict__ eb, __half* __restrict__ bias)
{
    __shared__ float rows[128][68];
    __shared__ float W2T[16][68];
    __shared__ float meanv[128], rinvv[128], c1s[16], c2s[16];
    int tid = threadIdx.x;
    size_t base = (size_t)blockIdx.x * 128;

#pragma unroll
    for (int r = 0; r < 16; r++) {
        int id  = tid + r * 128;
        int row = id >> 4;
        int c4  = (id & 15) * 4;
        *(float4*)&rows[row][c4] = *(const float4*)(p + (base + row) * 64 + c4);
    }
    for (int i = tid; i < 1024; i += 128) {
        int h = i >> 6, k = i & 63;
        W2T[h][k] = ew[i] * lnw[k];
    }
    if (tid < 16) {
        float a = 0.f, b2 = 0.f;
        for (int k = 0; k < 64; k++) {
            float e = ew[tid * 64 + k];
            a  += lnw[k] * e;
            b2 += lnb[k] * e;
        }
        c1s[tid] = a;
        c2s[tid] = b2 + eb[tid];
    }
    __syncthreads();

    {
        float s = 0.f, ss = 0.f;
#pragma unroll
        for (int q = 0; q < 16; q++) {
            float4 x = *(const float4*)&rows[tid][q * 4];
            s  += x.x + x.y + x.z + x.w;
            ss += x.x*x.x + x.y*x.y + x.z*x.z + x.w*x.w;
        }
        float mean = s * (1.0f / 64.0f);
        float var  = ss * (1.0f / 64.0f) - mean * mean;
        meanv[tid] = mean;
        rinvv[tid] = rsqrtf(var + EPSF);
    }
    __syncthreads();

    int warp = tid >> 5, lane = tid & 31;
    int g = lane >> 2, t = lane & 3;
    float acc[2][2][4];
#pragma unroll
    for (int i = 0; i < 2; i++)
#pragma unroll
        for (int j = 0; j < 2; j++)
#pragma unroll
            for (int q = 0; q < 4; q++) acc[i][j][q] = 0.f;

#pragma unroll
    for (int ks = 0; ks < 8; ks++) {
        int kk = ks * 8;
        uint32_t af[2][4];
#pragma unroll
        for (int mt = 0; mt < 2; mt++) {
            int r0 = warp * 32 + mt * 16 + g;
            af[mt][0] = __float_as_uint(rows[r0][kk + t]);
            af[mt][1] = __float_as_uint(rows[r0 + 8][kk + t]);
            af[mt][2] = __float_as_uint(rows[r0][kk + t + 4]);
            af[mt][3] = __float_as_uint(rows[r0 + 8][kk + t + 4]);
        }
        uint32_t bf[2][2];
#pragma unroll
        for (int nt = 0; nt < 2; nt++) {
            int c0 = nt * 8 + g;
            bf[nt][0] = __float_as_uint(W2T[c0][kk + t]);
            bf[nt][1] = __float_as_uint(W2T[c0][kk + t + 4]);
        }
#pragma unroll
        for (int mt = 0; mt < 2; mt++)
#pragma unroll
            for (int nt = 0; nt < 2; nt++)
                mma_tf32(acc[mt][nt], af[mt], bf[nt]);
    }

    int b  = (int)(base >> 18);
    int ij = (int)(base & 262143);
    int i  = ij >> 9;
    int j0 = ij & 511;
    __half* bb = bias + (((size_t)b * 16) * 512 + i) * 512 + j0;
#pragma unroll
    for (int mt = 0; mt < 2; mt++) {
#pragma unroll
        for (int half = 0; half < 2; half++) {
            int rl = warp * 32 + mt * 16 + g + half * 8;
            float m  = meanv[rl];
            float rv = rinvv[rl];
#pragma unroll
            for (int nt = 0; nt < 2; nt++) {
#pragma unroll
                for (int c = 0; c < 2; c++) {
                    int h = nt * 8 + 2 * t + c;
                    bb[(size_t)h * 512 * 512 + rl] =
                        __float2half(rv * (acc[mt][nt][half * 2 + c] - m * c1s[h]) + c2s[h]);
                }
            }
        }
    }
}

// ---------------- fused flash attention: S=QK^T/8+bias, online softmax, O=P@V ----------------
// grid (4 i-tiles, 64 bh), 256 threads (8 warps x 16 rows).
#define FL_SMEM ((128*68 + 64*68 + 64*68 + 128*68) * 4)
__global__ void __launch_bounds__(256) flash_attn(
    const __half* __restrict__ bias, const float* __restrict__ qkv, float* __restrict__ o)
{
    extern __shared__ float fsm[];
    float* Qs = fsm;                    // [128][68]
    float* Ks = Qs + 128 * 68;          // [64][68]
    float* Vs = Ks + 64 * 68;           // [64][68]
    float* Ps = Vs + 64 * 68;           // [128][68]

    int bh = blockIdx.y; int b = bh >> 4, h = bh & 15;
    int i0 = blockIdx.x * 128;
    int tid  = threadIdx.x;
    int warp = tid >> 5, lane = tid & 31;
    int g = lane >> 2, t = lane & 3;
    int r0 = warp * 16 + g;

    const float* qb = qkv + (size_t)(b * CL) * (3 * CD) + h * CDH;
    const float* kb = qb + CD;
    const float* vb = qb + 2 * CD;
    const __half* bbase = bias + ((size_t)bh * CL + i0) * CL;

#pragma unroll
    for (int r = 0; r < 8; r++) {
        int id  = tid + r * 256;
        int row = id >> 4;
        int c4  = (id & 15) * 4;
        *(float4*)&Qs[row * 68 + c4] = *(const float4*)(qb + (size_t)(i0 + row) * (3 * CD) + c4);
    }

    float Oa[8][4];
#pragma unroll
    for (int nt = 0; nt < 8; nt++)
#pragma unroll
        for (int q = 0; q < 4; q++) Oa[nt][q] = 0.f;
    float m0 = -1e30f, m1 = -1e30f, l0 = 0.f, l1 = 0.f;

    for (int j0 = 0; j0 < CL; j0 += 64) {
        __syncthreads();
#pragma unroll
        for (int r = 0; r < 4; r++) {
            int id  = tid + r * 256;
            int row = id >> 4;
            int c4  = (id & 15) * 4;
            *(float4*)&Ks[row * 68 + c4] = *(const float4*)(kb + (size_t)(j0 + row) * (3 * CD) + c4);
            *(float4*)&Vs[row * 68 + c4] = *(const float4*)(vb + (size_t)(j0 + row) * (3 * CD) + c4);
        }
        __syncthreads();

        // S = Q K^T (tf32)
        float sa[8][4];
#pragma unroll
        for (int nt = 0; nt < 8; nt++)
#pragma unroll
            for (int q = 0; q < 4; q++) sa[nt][q] = 0.f;
#pragma unroll
        for (int ks = 0; ks < 8; ks++) {
            int kk = ks * 8;
            uint32_t af[4];
            af[0] = __float_as_uint(Qs[r0 * 68 + kk + t]);
            af[1] = __float_as_uint(Qs[(r0 + 8) * 68 + kk + t]);
            af[2] = __float_as_uint(Qs[r0 * 68 + kk + t + 4]);
            af[3] = __float_as_uint(Qs[(r0 + 8) * 68 + kk + t + 4]);
#pragma unroll
            for (int nt = 0; nt < 8; nt++) {
                int c0 = nt * 8 + g;
                uint32_t bf[2];
                bf[0] = __float_as_uint(Ks[c0 * 68 + kk + t]);
                bf[1] = __float_as_uint(Ks[c0 * 68 + kk + t + 4]);
                mma_tf32(sa[nt], af, bf);
            }
        }

        // finish S: *1/8 + bias(half); track row maxima
        float mt0 = -1e30f, mt1 = -1e30f;
#pragma unroll
        for (int nt = 0; nt < 8; nt++) {
            int col = j0 + nt * 8 + 2 * t;
            float2 b0 = __half22float2(*(const __half2*)(bbase + (size_t)r0 * CL + col));
            float2 b1 = __half22float2(*(const __half2*)(bbase + (size_t)(r0 + 8) * CL + col));
            sa[nt][0] = fmaf(sa[nt][0], 0.125f, b0.x);
            sa[nt][1] = fmaf(sa[nt][1], 0.125f, b0.y);
            sa[nt][2] = fmaf(sa[nt][2], 0.125f, b1.x);
            sa[nt][3] = fmaf(sa[nt][3], 0.125f, b1.y);
            mt0 = fmaxf(mt0, fmaxf(sa[nt][0], sa[nt][1]));
            mt1 = fmaxf(mt1, fmaxf(sa[nt][2], sa[nt][3]));
        }
#pragma unroll
        for (int x = 1; x <= 2; x <<= 1) {
            mt0 = fmaxf(mt0, __shfl_xor_sync(0xffffffffu, mt0, x));
            mt1 = fmaxf(mt1, __shfl_xor_sync(0xffffffffu, mt1, x));
        }
        float mn0 = fmaxf(m0, mt0), mn1 = fmaxf(m1, mt1);
        // polynomial expf (FMA pipe) — NOT __expf (MUFU rt=8 is the scarce pipe here)
        float sc0 = expf(m0 - mn0), sc1 = expf(m1 - mn1);
        m0 = mn0; m1 = mn1;

        float ps0 = 0.f, ps1 = 0.f;
#pragma unroll
        for (int nt = 0; nt < 8; nt++) {
            int jl = nt * 8 + 2 * t;
            float p00 = expf(sa[nt][0] - m0);
            float p01 = expf(sa[nt][1] - m0);
            float p10 = expf(sa[nt][2] - m1);
            float p11 = expf(sa[nt][3] - m1);
            ps0 += p00 + p01; ps1 += p10 + p11;
            float2 w0; w0.x = p00; w0.y = p01;
            float2 w1; w1.x = p10; w1.y = p11;
            *(float2*)&Ps[r0 * 68 + jl] = w0;
            *(float2*)&Ps[(r0 + 8) * 68 + jl] = w1;
        }
#pragma unroll
        for (int x = 1; x <= 2; x <<= 1) {
            ps0 += __shfl_xor_sync(0xffffffffu, ps0, x);
            ps1 += __shfl_xor_sync(0xffffffffu, ps1, x);
        }
        l0 = l0 * sc0 + ps0;
        l1 = l1 * sc1 + ps1;

#pragma unroll
        for (int nt = 0; nt < 8; nt++) {
            Oa[nt][0] *= sc0; Oa[nt][1] *= sc0;
            Oa[nt][2] *= sc1; Oa[nt][3] *= sc1;
        }
        __syncwarp();

        // O += P @ V (tf32)
#pragma unroll
        for (int ks = 0; ks < 8; ks++) {
            int kk = ks * 8;
            uint32_t af[4];
            af[0] = __float_as_uint(Ps[r0 * 68 + kk + t]);
            af[1] = __float_as_uint(Ps[(r0 + 8) * 68 + kk + t]);
            af[2] = __float_as_uint(Ps[r0 * 68 + kk + t + 4]);
            af[3] = __float_as_uint(Ps[(r0 + 8) * 68 + kk + t + 4]);
#pragma unroll
            for (int nt = 0; nt < 8; nt++) {
                int c0 = nt * 8 + g;
                uint32_t bf[2];
                bf[0] = __float_as_uint(Vs[(kk + t) * 68 + c0]);
                bf[1] = __float_as_uint(Vs[(kk + t + 4) * 68 + c0]);
                mma_tf32(Oa[nt], af, bf);
            }
        }
    }

    float il0 = 1.0f / l0, il1 = 1.0f / l1;
    float* o0 = o + (size_t)(b * CL + i0 + r0) * CD + h * CDH;
    float* o1 = o + (size_t)(b * CL + i0 + r0 + 8) * CD + h * CDH;
#pragma unroll
    for (int nt = 0; nt < 8; nt++) {
        int d = nt * 8 + 2 * t;
        float2 w0; w0.x = Oa[nt][0] * il0; w0.y = Oa[nt][1] * il0;
        float2 w1; w1.x = Oa[nt][2] * il1; w1.y = Oa[nt][3] * il1;
        *(float2*)(o0 + d) = w0;
        *(float2*)(o1 + d) = w1;
    }
}

// ---------------- launch ----------------
extern "C" void kernel_launch(void* const* d_in, const int* in_sizes, int n_in,
                              void* d_out, int out_size)
{
    const float* h_in  = (const float*)d_in[0];
    const float* s_in  = (const float*)d_in[1];
    const float* p_in  = (const float*)d_in[2];
    const float* aln_w = (const float*)d_in[3];
    const float* aln_b = (const float*)d_in[4];
    const float* aw1   = (const float*)d_in[5];
    const float* ab1   = (const float*)d_in[6];
    const float* aw2   = (const float*)d_in[7];
    const float* ab2   = (const float*)d_in[8];
    const float* eln_w = (const float*)d_in[9];
    const float* eln_b = (const float*)d_in[10];
    const float* ew    = (const float*)d_in[11];
    const float* eb    = (const float*)d_in[12];
    const float* in_w  = (const float*)d_in[13];
    const float* in_b  = (const float*)d_in[14];
    const float* out_w = (const float*)d_in[15];
    const float* out_b = (const float*)d_in[16];
    const float* mw1   = (const float*)d_in[17];
    const float* mb1   = (const float*)d_in[18];
    const float* mw2   = (const float*)d_in[19];
    const float* mb2   = (const float*)d_in[20];
    float* out = (float*)d_out;

    float *sln, *t1, *mod, *x, *qkv, *o, *h2, *t2;
    __half* biasb;
    cudaGetSymbolAddress((void**)&sln,    g_sln);
    cudaGetSymbolAddress((void**)&t1,     g_t1);
    cudaGetSymbolAddress((void**)&mod,    g_mod);
    cudaGetSymbolAddress((void**)&biasb,  g_bias);
    cudaGetSymbolAddress((void**)&x,      g_x);
    cudaGetSymbolAddress((void**)&qkv,    g_qkv);
    cudaGetSymbolAddress((void**)&o,      g_o);
    cudaGetSymbolAddress((void**)&h2,     g_h2);
    cudaGetSymbolAddress((void**)&t2,     g_t2);

    cudaFuncSetAttribute(gemm_fp16<0>, cudaFuncAttributeMaxDynamicSharedMemorySize, GEMM_SMEM_H);
    cudaFuncSetAttribute(gemm_fp16<1>, cudaFuncAttributeMaxDynamicSharedMemorySize, GEMM_SMEM_H);
    cudaFuncSetAttribute(gemm_fp16<2>, cudaFuncAttributeMaxDynamicSharedMemorySize, GEMM_SMEM_H);
    cudaFuncSetAttribute(flash_attn,   cudaFuncAttributeMaxDynamicSharedMemorySize, FL_SMEM);

    // adaLN modulation chain
    ln_affine512<<<NTOK, 128>>>(s_in, aln_w, aln_b, sln);
    gemm_fp16<1><<<dim3(CND / 128, NTOK / 128), 256, GEMM_SMEM_H>>>(sln, aw1, ab1, t1,
        NTOK, CND, CND, nullptr, nullptr, 0);
    gemm_fp16<0><<<dim3(MODW / 128, NTOK / 128), 256, GEMM_SMEM_H>>>(t1, aw2, ab2, mod,
        NTOK, MODW, CND, nullptr, nullptr, 0);

    // edge bias (fp16)
    edge_bias_mma<<<(CB * CL * CL) / 128, 128>>>(p_in, eln_w, eln_b, ew, eb, biasb);

    // attention branch
    ln_mod1024<<<NTOK, 256>>>(h_in, mod, /*scale*/CD, /*shift*/0, x);
    gemm_fp16<0><<<dim3(3 * CD / 128, NTOK / 128), 256, GEMM_SMEM_H>>>(x, in_w, in_b, qkv,
        NTOK, 3 * CD, CD, nullptr, nullptr, 0);
    flash_attn<<<dim3(CL / 128, CB * CH), 256, FL_SMEM>>>(biasb, qkv, o);
    gemm_fp16<2><<<dim3(CD / 128, NTOK / 128), 256, GEMM_SMEM_H>>>(o, out_w, out_b, h2,
        NTOK, CD, CD, h_in, mod, 2 * CD);

    // gated MLP branch
    ln_mod1024<<<NTOK, 256>>>(h2, mod, /*scale*/4 * CD, /*shift*/3 * CD, x);
    gemm_fp16<1><<<dim3(CMLP / 128, NTOK / 128), 256, GEMM_SMEM_H>>>(x, mw1, mb1, t2,
        NTOK, CMLP, CD, nullptr, nullptr, 0);
    gemm_fp16<2><<<dim3(CD / 128, NTOK / 128), 256, GEMM_SMEM_H>>>(t2, mw2, mb2, out,
        NTOK, CD, CMLP, h2, mod, 5 * CD);
}

// round 10
// speedup vs baseline: 1.2711x; 1.1403x over previous
#include <cuda_runtime.h>
#include <cuda_fp16.h>
#include <math.h>
#include <stdint.h>

// Problem constants
#define CB   4
#define CL   512
#define CD   1024
#define CND  512
#define CED  64
#define CH   16
#define CMLP 2048
#define CDH  64
#define NTOK (CB*CL)        // 2048
#define MODW (6*CD)         // 6144
#define EPSF 1e-5f

// ---------------- scratch ----------------
__device__ __half g_sln_h[NTOK*CND];
__device__ __half g_t1_h[NTOK*CND];
__device__ float  g_mod[NTOK*MODW];
__device__ __half g_bias[(size_t)CB*CH*CL*CL];
__device__ __half g_x_h[NTOK*CD];
__device__ float  g_qkv[NTOK*3*CD];
__device__ __half g_o_h[NTOK*CD];
__device__ float  g_h2[NTOK*CD];
__device__ __half g_t2_h[NTOK*CMLP];
// fp16 weights: aw1 | aw2 | in_w | out_w | mw1 | mw2
#define OFF_AW1  0
#define OFF_AW2  (OFF_AW1 + 512*512)
#define OFF_INW  (OFF_AW2 + 6144*512)
#define OFF_OUTW (OFF_INW + 3072*1024)
#define OFF_MW1  (OFF_OUTW + 1024*1024)
#define OFF_MW2  (OFF_MW1 + 2048*1024)
#define WH_TOTAL (OFF_MW2 + 1024*2048)
__device__ __half g_wh[WH_TOTAL];

// ---------------- utils ----------------
__device__ __forceinline__ float warp_sum(float v) {
#pragma unroll
    for (int o = 16; o > 0; o >>= 1) v += __shfl_xor_sync(0xffffffffu, v, o);
    return v;
}
__device__ __forceinline__ void mma_tf32(float c[4], const uint32_t a[4], const uint32_t b[2]) {
    asm volatile(
        "mma.sync.aligned.m16n8k8.row.col.f32.tf32.tf32.f32 "
        "{%0,%1,%2,%3}, {%4,%5,%6,%7}, {%8,%9}, {%0,%1,%2,%3};"
        : "+f"(c[0]), "+f"(c[1]), "+f"(c[2]), "+f"(c[3])
        : "r"(a[0]), "r"(a[1]), "r"(a[2]), "r"(a[3]), "r"(b[0]), "r"(b[1]));
}
__device__ __forceinline__ void mma_fp16(float c[4], const uint32_t a[4], const uint32_t b[2]) {
    asm volatile(
        "mma.sync.aligned.m16n8k16.row.col.f32.f16.f16.f32 "
        "{%0,%1,%2,%3}, {%4,%5,%6,%7}, {%8,%9}, {%0,%1,%2,%3};"
        : "+f"(c[0]), "+f"(c[1]), "+f"(c[2]), "+f"(c[3])
        : "r"(a[0]), "r"(a[1]), "r"(a[2]), "r"(a[3]), "r"(b[0]), "r"(b[1]));
}
__device__ __forceinline__ uint32_t pack_h2(float lo, float hi) {
    __half2 h = __floats2half2_rn(lo, hi);
    return *(uint32_t*)&h;
}
#define CP_ASYNC16(dst_u32, src_ptr) \
    asm volatile("cp.async.cg.shared.global [%0], [%1], 16;" :: "r"(dst_u32), "l"(src_ptr))
#define CP_COMMIT() asm volatile("cp.async.commit_group;")
#define CP_WAIT(n)  asm volatile("cp.async.wait_group %0;" :: "n"(n))

// ---------------- fp32 -> fp16 converter ----------------
__global__ void __launch_bounds__(256) cvt_fp16(
    const float4* __restrict__ src, uint2* __restrict__ dst, int n4)
{
    for (int i = blockIdx.x * 256 + threadIdx.x; i < n4; i += gridDim.x * 256) {
        float4 v = src[i];
        uint2 u;
        u.x = pack_h2(v.x, v.y);
        u.y = pack_h2(v.z, v.w);
        dst[i] = u;
    }
}

// ---------------- LN(s)*w+b -> half, width 512 ----------------
__global__ void __launch_bounds__(128) ln_affine512h(
    const float* __restrict__ x, const float* __restrict__ w,
    const float* __restrict__ b, __half* __restrict__ out)
{
    int row = blockIdx.x;
    const float4* xr = (const float4*)(x + (size_t)row * CND);
    float4 v = xr[threadIdx.x];
    float s  = v.x + v.y + v.z + v.w;
    float ss = v.x*v.x + v.y*v.y + v.z*v.z + v.w*v.w;
    s = warp_sum(s); ss = warp_sum(ss);
    __shared__ float sh[8];
    int wid = threadIdx.x >> 5, lid = threadIdx.x & 31;
    if (lid == 0) { sh[wid] = s; sh[4 + wid] = ss; }
    __syncthreads();
    s  = sh[0] + sh[1] + sh[2] + sh[3];
    ss = sh[4] + sh[5] + sh[6] + sh[7];
    float mean = s * (1.0f / CND);
    float var  = ss * (1.0f / CND) - mean * mean;
    float rinv = rsqrtf(var + EPSF);
    int d = threadIdx.x * 4;
    float4 wv = *(const float4*)(w + d);
    float4 bv = *(const float4*)(b + d);
    uint2 u;
    u.x = pack_h2((v.x - mean) * rinv * wv.x + bv.x, (v.y - mean) * rinv * wv.y + bv.y);
    u.y = pack_h2((v.z - mean) * rinv * wv.z + bv.z, (v.w - mean) * rinv * wv.w + bv.w);
    ((uint2*)(out + (size_t)row * CND))[threadIdx.x] = u;
}

// ---------------- LN(h)*(1+scale)+shift -> half, width 1024 ----------------
__global__ void __launch_bounds__(256) ln_mod1024h(
    const float* __restrict__ x, const float* __restrict__ mod,
    int scale_off, int shift_off, __half* __restrict__ out)
{
    int row = blockIdx.x;
    float4 v = ((const float4*)(x + (size_t)row * CD))[threadIdx.x];
    float s  = v.x + v.y + v.z + v.w;
    float ss = v.x*v.x + v.y*v.y + v.z*v.z + v.w*v.w;
    s = warp_sum(s); ss = warp_sum(ss);
    __shared__ float sh[16];
    int wid = threadIdx.x >> 5, lid = threadIdx.x & 31;
    if (lid == 0) { sh[wid] = s; sh[8 + wid] = ss; }
    __syncthreads();
    s = 0.f; ss = 0.f;
#pragma unroll
    for (int i = 0; i < 8; i++) { s += sh[i]; ss += sh[8 + i]; }
    float mean = s * (1.0f / CD);
    float var  = ss * (1.0f / CD) - mean * mean;
    float rinv = rsqrtf(var + EPSF);
    int d = threadIdx.x * 4;
    const float* mrow = mod + (size_t)row * MODW;
    float4 sc = *(const float4*)(mrow + scale_off + d);
    float4 sf = *(const float4*)(mrow + shift_off + d);
    uint2 u;
    u.x = pack_h2(((v.x - mean) * rinv) * (1.0f + sc.x) + sf.x,
                  ((v.y - mean) * rinv) * (1.0f + sc.y) + sf.y);
    u.y = pack_h2(((v.z - mean) * rinv) * (1.0f + sc.z) + sf.z,
                  ((v.w - mean) * rinv) * (1.0f + sc.w) + sf.w);
    ((uint2*)(out + (size_t)row * CD))[threadIdx.x] = u;
}

// ---------------- fp16 NT GEMM, cp.async 2-stage, fp16 operands in gmem ----------------
// C[M,N] = A[M,K] @ W[N,K]^T. Block 128x128x32, 256 threads.
// EPI 0: float C = acc + bias
// EPI 1: half  C = silu(acc + bias)
// EPI 2: float C = res + (acc + bias) * gate
#define GEMM_SMEM_H (2 * 2 * 128 * 20 * 4)   // 40 KB
template<int EPI>
__global__ void __launch_bounds__(256, 2) gemm_h(
    const __half* __restrict__ A, const __half* __restrict__ W,
    const float* __restrict__ bias, void* __restrict__ Cv,
    int M, int N, int K,
    const float* __restrict__ res, const float* __restrict__ gate, int gate_off)
{
    extern __shared__ uint32_t dynh[];
    uint32_t* As = dynh;                    // [2][128][20]
    uint32_t* Ws = dynh + 2 * 128 * 20;

    int bm = blockIdx.y * 128;
    int bn = blockIdx.x * 128;
    int tid  = threadIdx.x;
    int warp = tid >> 5, lane = tid & 31;
    int g = lane >> 2, t = lane & 3;
    int wm = (warp & 1) * 64;
    int wn = (warp >> 1) * 32;

    float acc[4][4][4];
#pragma unroll
    for (int i = 0; i < 4; i++)
#pragma unroll
        for (int j = 0; j < 4; j++)
#pragma unroll
            for (int q = 0; q < 4; q++) acc[i][j][q] = 0.f;

    // prologue: stage 0
#pragma unroll
    for (int cc = 0; cc < 2; cc++) {
        int c = tid + cc * 256;
        int row = c >> 2, seg = c & 3;
        uint32_t da = (uint32_t)__cvta_generic_to_shared(&As[row * 20 + seg * 4]);
        CP_ASYNC16(da, A + (size_t)(bm + row) * K + seg * 8);
        uint32_t dw = (uint32_t)__cvta_generic_to_shared(&Ws[row * 20 + seg * 4]);
        CP_ASYNC16(dw, W + (size_t)(bn + row) * K + seg * 8);
    }
    CP_COMMIT();

    int nIter = K >> 5;
    for (int it = 0; it < nIter; ++it) {
        if (it + 1 < nIter) {
            int k0n = (it + 1) << 5;
            int stn = (it + 1) & 1;
            uint32_t* An = As + (size_t)stn * 128 * 20;
            uint32_t* Wn = Ws + (size_t)stn * 128 * 20;
#pragma unroll
            for (int cc = 0; cc < 2; cc++) {
                int c = tid + cc * 256;
                int row = c >> 2, seg = c & 3;
                uint32_t da = (uint32_t)__cvta_generic_to_shared(&An[row * 20 + seg * 4]);
                CP_ASYNC16(da, A + (size_t)(bm + row) * K + k0n + seg * 8);
                uint32_t dw = (uint32_t)__cvta_generic_to_shared(&Wn[row * 20 + seg * 4]);
                CP_ASYNC16(dw, W + (size_t)(bn + row) * K + k0n + seg * 8);
            }
            CP_COMMIT();
            CP_WAIT(1);
        } else {
            CP_WAIT(0);
        }
        __syncthreads();
        int st = it & 1;
        const uint32_t* Ab = As + (size_t)st * 128 * 20;
        const uint32_t* Wb = Ws + (size_t)st * 128 * 20;
#pragma unroll
        for (int ks = 0; ks < 2; ks++) {
            int kp = ks * 8;
            uint32_t af[4][4];
#pragma unroll
            for (int mt = 0; mt < 4; mt++) {
                int r0 = wm + mt * 16 + g;
                af[mt][0] = Ab[(size_t)r0 * 20 + kp + t];
                af[mt][1] = Ab[(size_t)(r0 + 8) * 20 + kp + t];
                af[mt][2] = Ab[(size_t)r0 * 20 + kp + t + 4];
                af[mt][3] = Ab[(size_t)(r0 + 8) * 20 + kp + t + 4];
            }
            uint32_t bf[4][2];
#pragma unroll
            for (int nt = 0; nt < 4; nt++) {
                int c0 = wn + nt * 8 + g;
                bf[nt][0] = Wb[(size_t)c0 * 20 + kp + t];
                bf[nt][1] = Wb[(size_t)c0 * 20 + kp + t + 4];
            }
#pragma unroll
            for (int mt = 0; mt < 4; mt++)
#pragma unroll
                for (int nt = 0; nt < 4; nt++)
                    mma_fp16(acc[mt][nt], af[mt], bf[nt]);
        }
        __syncthreads();
    }

#pragma unroll
    for (int mt = 0; mt < 4; mt++) {
#pragma unroll
        for (int half = 0; half < 2; half++) {
            int row = bm + wm + mt * 16 + g + half * 8;
            const float* rr = (EPI == 2) ? res + (size_t)row * N : nullptr;
            const float* gr = (EPI == 2) ? gate + (size_t)row * MODW + gate_off : nullptr;
#pragma unroll
            for (int nt = 0; nt < 4; nt++) {
                int col = bn + wn + nt * 8 + 2 * t;
                float v0 = acc[mt][nt][half * 2 + 0] + bias[col];
                float v1 = acc[mt][nt][half * 2 + 1] + bias[col + 1];
                if (EPI == 1) {
                    v0 = v0 / (1.0f + expf(-v0));
                    v1 = v1 / (1.0f + expf(-v1));
                    __half* cr = (__half*)Cv + (size_t)row * N;
                    *(uint32_t*)(cr + col) = pack_h2(v0, v1);
                } else {
                    if (EPI == 2) {
                        v0 = rr[col]     + v0 * gr[col];
                        v1 = rr[col + 1] + v1 * gr[col + 1];
                    }
                    float* cr = (float*)Cv + (size_t)row * N;
                    float2 o2; o2.x = v0; o2.y = v1;
                    *(float2*)(cr + col) = o2;
                }
            }
        }
    }
}

// ---------------- edge bias (unchanged from round 9) ----------------
__global__ void __launch_bounds__(128) edge_bias_mma(
    const float* __restrict__ p, const float* __restrict__ lnw, const float* __restrict__ lnb,
    const float* __restrict__ ew, const float* __restrict__ eb, __half* __restrict__ bias)
{
    __shared__ float rows[128][68];
    __shared__ float W2T[16][68];
    __shared__ float meanv[128], rinvv[128], c1s[16], c2s[16];
    int tid = threadIdx.x;
    size_t base = (size_t)blockIdx.x * 128;

#pragma unroll
    for (int r = 0; r < 16; r++) {
        int id  = tid + r * 128;
        int row = id >> 4;
        int c4  = (id & 15) * 4;
        *(float4*)&rows[row][c4] = *(const float4*)(p + (base + row) * 64 + c4);
    }
    for (int i = tid; i < 1024; i += 128) {
        int h = i >> 6, k = i & 63;
        W2T[h][k] = ew[i] * lnw[k];
    }
    if (tid < 16) {
        float a = 0.f, b2 = 0.f;
        for (int k = 0; k < 64; k++) {
            float e = ew[tid * 64 + k];
            a  += lnw[k] * e;
            b2 += lnb[k] * e;
        }
        c1s[tid] = a;
        c2s[tid] = b2 + eb[tid];
    }
    __syncthreads();

    {
        float s = 0.f, ss = 0.f;
#pragma unroll
        for (int q = 0; q < 16; q++) {
            float4 x = *(const float4*)&rows[tid][q * 4];
            s  += x.x + x.y + x.z + x.w;
            ss += x.x*x.x + x.y*x.y + x.z*x.z + x.w*x.w;
        }
        float mean = s * (1.0f / 64.0f);
        float var  = ss * (1.0f / 64.0f) - mean * mean;
        meanv[tid] = mean;
        rinvv[tid] = rsqrtf(var + EPSF);
    }
    __syncthreads();

    int warp = tid >> 5, lane = tid & 31;
    int g = lane >> 2, t = lane & 3;
    float acc[2][2][4];
#pragma unroll
    for (int i = 0; i < 2; i++)
#pragma unroll
        for (int j = 0; j < 2; j++)
#pragma unroll
            for (int q = 0; q < 4; q++) acc[i][j][q] = 0.f;

#pragma unroll
    for (int ks = 0; ks < 8; ks++) {
        int kk = ks * 8;
        uint32_t af[2][4];
#pragma unroll
        for (int mt = 0; mt < 2; mt++) {
            int r0 = warp * 32 + mt * 16 + g;
            af[mt][0] = __float_as_uint(rows[r0][kk + t]);
            af[mt][1] = __float_as_uint(rows[r0 + 8][kk + t]);
            af[mt][2] = __float_as_uint(rows[r0][kk + t + 4]);
            af[mt][3] = __float_as_uint(rows[r0 + 8][kk + t + 4]);
        }
        uint32_t bf[2][2];
#pragma unroll
        for (int nt = 0; nt < 2; nt++) {
            int c0 = nt * 8 + g;
            bf[nt][0] = __float_as_uint(W2T[c0][kk + t]);
            bf[nt][1] = __float_as_uint(W2T[c0][kk + t + 4]);
        }
#pragma unroll
        for (int mt = 0; mt < 2; mt++)
#pragma unroll
            for (int nt = 0; nt < 2; nt++)
                mma_tf32(acc[mt][nt], af[mt], bf[nt]);
    }

    int b  = (int)(base >> 18);
    int ij = (int)(base & 262143);
    int i  = ij >> 9;
    int j0 = ij & 511;
    __half* bb = bias + (((size_t)b * 16) * 512 + i) * 512 + j0;
#pragma unroll
    for (int mt = 0; mt < 2; mt++) {
#pragma unroll
        for (int half = 0; half < 2; half++) {
            int rl = warp * 32 + mt * 16 + g + half * 8;
            float m  = meanv[rl];
            float rv = rinvv[rl];
#pragma unroll
            for (int nt = 0; nt < 2; nt++) {
#pragma unroll
                for (int c = 0; c < 2; c++) {
                    int h = nt * 8 + 2 * t + c;
                    bb[(size_t)h * 512 * 512 + rl] =
                        __float2half(rv * (acc[mt][nt][half * 2 + c] - m * c1s[h]) + c2s[h]);
                }
            }
        }
    }
}

// ---------------- fused flash attention (o out as half) ----------------
#define FL_SMEM ((128*68 + 64*68 + 64*68 + 128*68) * 4)
__global__ void __launch_bounds__(256) flash_attn(
    const __half* __restrict__ bias, const float* __restrict__ qkv, __half* __restrict__ o)
{
    extern __shared__ float fsm[];
    float* Qs = fsm;
    float* Ks = Qs + 128 * 68;
    float* Vs = Ks + 64 * 68;
    float* Ps = Vs + 64 * 68;

    int bh = blockIdx.y; int b = bh >> 4, h = bh & 15;
    int i0 = blockIdx.x * 128;
    int tid  = threadIdx.x;
    int warp = tid >> 5, lane = tid & 31;
    int g = lane >> 2, t = lane & 3;
    int r0 = warp * 16 + g;

    const float* qb = qkv + (size_t)(b * CL) * (3 * CD) + h * CDH;
    const float* kb = qb + CD;
    const float* vb = qb + 2 * CD;
    const __half* bbase = bias + ((size_t)bh * CL + i0) * CL;

#pragma unroll
    for (int r = 0; r < 8; r++) {
        int id  = tid + r * 256;
        int row = id >> 4;
        int c4  = (id & 15) * 4;
        *(float4*)&Qs[row * 68 + c4] = *(const float4*)(qb + (size_t)(i0 + row) * (3 * CD) + c4);
    }

    float Oa[8][4];
#pragma unroll
    for (int nt = 0; nt < 8; nt++)
#pragma unroll
        for (int q = 0; q < 4; q++) Oa[nt][q] = 0.f;
    float m0 = -1e30f, m1 = -1e30f, l0 = 0.f, l1 = 0.f;

    for (int j0 = 0; j0 < CL; j0 += 64) {
        __syncthreads();
#pragma unroll
        for (int r = 0; r < 4; r++) {
            int id  = tid + r * 256;
            int row = id >> 4;
            int c4  = (id & 15) * 4;
            *(float4*)&Ks[row * 68 + c4] = *(const float4*)(kb + (size_t)(j0 + row) * (3 * CD) + c4);
            *(float4*)&Vs[row * 68 + c4] = *(const float4*)(vb + (size_t)(j0 + row) * (3 * CD) + c4);
        }
        __syncthreads();

        float sa[8][4];
#pragma unroll
        for (int nt = 0; nt < 8; nt++)
#pragma unroll
            for (int q = 0; q < 4; q++) sa[nt][q] = 0.f;
#pragma unroll
        for (int ks = 0; ks < 8; ks++) {
            int kk = ks * 8;
            uint32_t af[4];
            af[0] = __float_as_uint(Qs[r0 * 68 + kk + t]);
            af[1] = __float_as_uint(Qs[(r0 + 8) * 68 + kk + t]);
            af[2] = __float_as_uint(Qs[r0 * 68 + kk + t + 4]);
            af[3] = __float_as_uint(Qs[(r0 + 8) * 68 + kk + t + 4]);
#pragma unroll
            for (int nt = 0; nt < 8; nt++) {
                int c0 = nt * 8 + g;
                uint32_t bf[2];
                bf[0] = __float_as_uint(Ks[c0 * 68 + kk + t]);
                bf[1] = __float_as_uint(Ks[c0 * 68 + kk + t + 4]);
                mma_tf32(sa[nt], af, bf);
            }
        }

        float mt0 = -1e30f, mt1 = -1e30f;
#pragma unroll
        for (int nt = 0; nt < 8; nt++) {
            int col = j0 + nt * 8 + 2 * t;
            float2 b0 = __half22float2(*(const __half2*)(bbase + (size_t)r0 * CL + col));
            float2 b1 = __half22float2(*(const __half2*)(bbase + (size_t)(r0 + 8) * CL + col));
            sa[nt][0] = fmaf(sa[nt][0], 0.125f, b0.x);
            sa[nt][1] = fmaf(sa[nt][1], 0.125f, b0.y);
            sa[nt][2] = fmaf(sa[nt][2], 0.125f, b1.x);
            sa[nt][3] = fmaf(sa[nt][3], 0.125f, b1.y);
            mt0 = fmaxf(mt0, fmaxf(sa[nt][0], sa[nt][1]));
            mt1 = fmaxf(mt1, fmaxf(sa[nt][2], sa[nt][3]));
        }
#pragma unroll
        for (int x = 1; x <= 2; x <<= 1) {
            mt0 = fmaxf(mt0, __shfl_xor_sync(0xffffffffu, mt0, x));
            mt1 = fmaxf(mt1, __shfl_xor_sync(0xffffffffu, mt1, x));
        }
        float mn0 = fmaxf(m0, mt0), mn1 = fmaxf(m1, mt1);
        float sc0 = expf(m0 - mn0), sc1 = expf(m1 - mn1);
        m0 = mn0; m1 = mn1;

        float ps0 = 0.f, ps1 = 0.f;
#pragma unroll
        for (int nt = 0; nt < 8; nt++) {
            int jl = nt * 8 + 2 * t;
            float p00 = expf(sa[nt][0] - m0);
            float p01 = expf(sa[nt][1] - m0);
            float p10 = expf(sa[nt][2] - m1);
            float p11 = expf(sa[nt][3] - m1);
            ps0 += p00 + p01; ps1 += p10 + p11;
            float2 w0; w0.x = p00; w0.y = p01;
            float2 w1; w1.x = p10; w1.y = p11;
            *(float2*)&Ps[r0 * 68 + jl] = w0;
            *(float2*)&Ps[(r0 + 8) * 68 + jl] = w1;
        }
#pragma unroll
        for (int x = 1; x <= 2; x <<= 1) {
            ps0 += __shfl_xor_sync(0xffffffffu, ps0, x);
            ps1 += __shfl_xor_sync(0xffffffffu, ps1, x);
        }
        l0 = l0 * sc0 + ps0;
        l1 = l1 * sc1 + ps1;

#pragma unroll
        for (int nt = 0; nt < 8; nt++) {
            Oa[nt][0] *= sc0; Oa[nt][1] *= sc0;
            Oa[nt][2] *= sc1; Oa[nt][3] *= sc1;
        }
        __syncwarp();

#pragma unroll
        for (int ks = 0; ks < 8; ks++) {
            int kk = ks * 8;
            uint32_t af[4];
            af[0] = __float_as_uint(Ps[r0 * 68 + kk + t]);
            af[1] = __float_as_uint(Ps[(r0 + 8) * 68 + kk + t]);
            af[2] = __float_as_uint(Ps[r0 * 68 + kk + t + 4]);
            af[3] = __float_as_uint(Ps[(r0 + 8) * 68 + kk + t + 4]);
#pragma unroll
            for (int nt = 0; nt < 8; nt++) {
                int c0 = nt * 8 + g;
                uint32_t bf[2];
                bf[0] = __float_as_uint(Vs[(kk + t) * 68 + c0]);
                bf[1] = __float_as_uint(Vs[(kk + t + 4) * 68 + c0]);
                mma_tf32(Oa[nt], af, bf);
            }
        }
    }

    float il0 = 1.0f / l0, il1 = 1.0f / l1;
    __half* o0 = o + (size_t)(b * CL + i0 + r0) * CD + h * CDH;
    __half* o1 = o + (size_t)(b * CL + i0 + r0 + 8) * CD + h * CDH;
#pragma unroll
    for (int nt = 0; nt < 8; nt++) {
        int d = nt * 8 + 2 * t;
        *(uint32_t*)(o0 + d) = pack_h2(Oa[nt][0] * il0, Oa[nt][1] * il0);
        *(uint32_t*)(o1 + d) = pack_h2(Oa[nt][2] * il1, Oa[nt][3] * il1);
    }
}

// ---------------- launch ----------------
extern "C" void kernel_launch(void* const* d_in, const int* in_sizes, int n_in,
                              void* d_out, int out_size)
{
    const float* h_in  = (const float*)d_in[0];
    const float* s_in  = (const float*)d_in[1];
    const float* p_in  = (const float*)d_in[2];
    const float* aln_w = (const float*)d_in[3];
    const float* aln_b = (const float*)d_in[4];
    const float* aw1   = (const float*)d_in[5];
    const float* ab1   = (const float*)d_in[6];
    const float* aw2   = (const float*)d_in[7];
    const float* ab2   = (const float*)d_in[8];
    const float* eln_w = (const float*)d_in[9];
    const float* eln_b = (const float*)d_in[10];
    const float* ew    = (const float*)d_in[11];
    const float* eb    = (const float*)d_in[12];
    const float* in_w  = (const float*)d_in[13];
    const float* in_b  = (const float*)d_in[14];
    const float* out_w = (const float*)d_in[15];
    const float* out_b = (const float*)d_in[16];
    const float* mw1   = (const float*)d_in[17];
    const float* mb1   = (const float*)d_in[18];
    const float* mw2   = (const float*)d_in[19];
    const float* mb2   = (const float*)d_in[20];
    float* out = (float*)d_out;

    float *mod, *qkv, *h2;
    __half *sln_h, *t1_h, *x_h, *o_h, *t2_h, *biasb, *wh;
    cudaGetSymbolAddress((void**)&sln_h, g_sln_h);
    cudaGetSymbolAddress((void**)&t1_h,  g_t1_h);
    cudaGetSymbolAddress((void**)&mod,   g_mod);
    cudaGetSymbolAddress((void**)&biasb, g_bias);
    cudaGetSymbolAddress((void**)&x_h,   g_x_h);
    cudaGetSymbolAddress((void**)&qkv,   g_qkv);
    cudaGetSymbolAddress((void**)&o_h,   g_o_h);
    cudaGetSymbolAddress((void**)&h2,    g_h2);
    cudaGetSymbolAddress((void**)&t2_h,  g_t2_h);
    cudaGetSymbolAddress((void**)&wh,    g_wh);

    cudaFuncSetAttribute(gemm_h<0>, cudaFuncAttributeMaxDynamicSharedMemorySize, GEMM_SMEM_H);
    cudaFuncSetAttribute(gemm_h<1>, cudaFuncAttributeMaxDynamicSharedMemorySize, GEMM_SMEM_H);
    cudaFuncSetAttribute(gemm_h<2>, cudaFuncAttributeMaxDynamicSharedMemorySize, GEMM_SMEM_H);
    cudaFuncSetAttribute(flash_attn, cudaFuncAttributeMaxDynamicSharedMemorySize, FL_SMEM);

    // weight conversion (fp32 -> fp16), once per launch
    cvt_fp16<<<256, 256>>>((const float4*)aw1,   (uint2*)(wh + OFF_AW1),  512*512/4);
    cvt_fp16<<<512, 256>>>((const float4*)aw2,   (uint2*)(wh + OFF_AW2),  6144*512/4);
    cvt_fp16<<<512, 256>>>((const float4*)in_w,  (uint2*)(wh + OFF_INW),  3072*1024/4);
    cvt_fp16<<<512, 256>>>((const float4*)out_w, (uint2*)(wh + OFF_OUTW), 1024*1024/4);
    cvt_fp16<<<512, 256>>>((const float4*)mw1,   (uint2*)(wh + OFF_MW1),  2048*1024/4);
    cvt_fp16<<<512, 256>>>((const float4*)mw2,   (uint2*)(wh + OFF_MW2),  1024*2048/4);

    // adaLN modulation chain
    ln_affine512h<<<NTOK, 128>>>(s_in, aln_w, aln_b, sln_h);
    gemm_h<1><<<dim3(CND / 128, NTOK / 128), 256, GEMM_SMEM_H>>>(sln_h, wh + OFF_AW1, ab1,
        t1_h, NTOK, CND, CND, nullptr, nullptr, 0);
    gemm_h<0><<<dim3(MODW / 128, NTOK / 128), 256, GEMM_SMEM_H>>>(t1_h, wh + OFF_AW2, ab2,
        mod, NTOK, MODW, CND, nullptr, nullptr, 0);

    // edge bias (fp16)
    edge_bias_mma<<<(CB * CL * CL) / 128, 128>>>(p_in, eln_w, eln_b, ew, eb, biasb);

    // attention branch
    ln_mod1024h<<<NTOK, 256>>>(h_in, mod, /*scale*/CD, /*shift*/0, x_h);
    gemm_h<0><<<dim3(3 * CD / 128, NTOK / 128), 256, GEMM_SMEM_H>>>(x_h, wh + OFF_INW, in_b,
        qkv, NTOK, 3 * CD, CD, nullptr, nullptr, 0);
    flash_attn<<<dim3(CL / 128, CB * CH), 256, FL_SMEM>>>(biasb, qkv, o_h);
    gemm_h<2><<<dim3(CD / 128, NTOK / 128), 256, GEMM_SMEM_H>>>(o_h, wh + OFF_OUTW, out_b,
        h2, NTOK, CD, CD, h_in, mod, 2 * CD);

    // gated MLP branch
    ln_mod1024h<<<NTOK, 256>>>(h2, mod, /*scale*/4 * CD, /*shift*/3 * CD, x_h);
    gemm_h<1><<<dim3(CMLP / 128, NTOK / 128), 256, GEMM_SMEM_H>>>(x_h, wh + OFF_MW1, mb1,
        t2_h, NTOK, CMLP, CD, nullptr, nullptr, 0);
    gemm_h<2><<<dim3(CD / 128, NTOK / 128), 256, GEMM_SMEM_H>>>(t2_h, wh + OFF_MW2, mb2,
        out, NTOK, CD, CMLP, h2, mod, 5 * CD);
}

// round 11
// speedup vs baseline: 1.3668x; 1.0753x over previous
#include <cuda_runtime.h>
#include <cuda_fp16.h>
#include <math.h>
#include <stdint.h>

// Problem constants
#define CB   4
#define CL   512
#define CD   1024
#define CND  512
#define CED  64
#define CH   16
#define CMLP 2048
#define CDH  64
#define NTOK (CB*CL)        // 2048
#define MODW (6*CD)         // 6144
#define EPSF 1e-5f

// ---------------- scratch ----------------
__device__ __half g_sln_h[NTOK*CND];
__device__ __half g_t1_h[NTOK*CND];
__device__ float  g_mod[NTOK*MODW];
__device__ __half g_bias[(size_t)CB*CH*CL*CL];
__device__ __half g_x_h[NTOK*CD];
__device__ __half g_qkv_h[NTOK*3*CD];
__device__ __half g_o_h[NTOK*CD];
__device__ float  g_h2[NTOK*CD];
__device__ __half g_t2_h[NTOK*CMLP];
// fp16 weights: aw1 | aw2 | in_w | out_w | mw1 | mw2
#define OFF_AW1  0
#define OFF_AW2  (OFF_AW1 + 512*512)
#define OFF_INW  (OFF_AW2 + 6144*512)
#define OFF_OUTW (OFF_INW + 3072*1024)
#define OFF_MW1  (OFF_OUTW + 1024*1024)
#define OFF_MW2  (OFF_MW1 + 2048*1024)
#define WH_TOTAL (OFF_MW2 + 1024*2048)
__device__ __half g_wh[WH_TOTAL];

// ---------------- utils ----------------
__device__ __forceinline__ float warp_sum(float v) {
#pragma unroll
    for (int o = 16; o > 0; o >>= 1) v += __shfl_xor_sync(0xffffffffu, v, o);
    return v;
}
__device__ __forceinline__ void mma_tf32(float c[4], const uint32_t a[4], const uint32_t b[2]) {
    asm volatile(
        "mma.sync.aligned.m16n8k8.row.col.f32.tf32.tf32.f32 "
        "{%0,%1,%2,%3}, {%4,%5,%6,%7}, {%8,%9}, {%0,%1,%2,%3};"
        : "+f"(c[0]), "+f"(c[1]), "+f"(c[2]), "+f"(c[3])
        : "r"(a[0]), "r"(a[1]), "r"(a[2]), "r"(a[3]), "r"(b[0]), "r"(b[1]));
}
__device__ __forceinline__ void mma_fp16(float c[4], const uint32_t a[4], const uint32_t b[2]) {
    asm volatile(
        "mma.sync.aligned.m16n8k16.row.col.f32.f16.f16.f32 "
        "{%0,%1,%2,%3}, {%4,%5,%6,%7}, {%8,%9}, {%0,%1,%2,%3};"
        : "+f"(c[0]), "+f"(c[1]), "+f"(c[2]), "+f"(c[3])
        : "r"(a[0]), "r"(a[1]), "r"(a[2]), "r"(a[3]), "r"(b[0]), "r"(b[1]));
}
__device__ __forceinline__ uint32_t pack_h2(float lo, float hi) {
    __half2 h = __floats2half2_rn(lo, hi);
    return *(uint32_t*)&h;
}
#define CP_ASYNC16(dst_u32, src_ptr) \
    asm volatile("cp.async.cg.shared.global [%0], [%1], 16;" :: "r"(dst_u32), "l"(src_ptr))
#define CP_COMMIT() asm volatile("cp.async.commit_group;")
#define CP_WAIT(n)  asm volatile("cp.async.wait_group %0;" :: "n"(n))

// ---------------- all weights fp32 -> fp16, one kernel ----------------
__global__ void __launch_bounds__(256) cvt_all(
    const float4* __restrict__ s0, const float4* __restrict__ s1,
    const float4* __restrict__ s2, const float4* __restrict__ s3,
    const float4* __restrict__ s4, const float4* __restrict__ s5,
    uint2* __restrict__ dst)
{
    const int n0 = 512*512/4, n1 = 6144*512/4, n2 = 3072*1024/4,
              n3 = 1024*1024/4, n4 = 2048*1024/4, n5 = 1024*2048/4;
    int total = n0 + n1 + n2 + n3 + n4 + n5;
    for (int i = blockIdx.x * 256 + threadIdx.x; i < total; i += gridDim.x * 256) {
        int j = i; const float4* s;
        if (j < n0) s = s0;
        else { j -= n0; if (j < n1) s = s1;
        else { j -= n1; if (j < n2) s = s2;
        else { j -= n2; if (j < n3) s = s3;
        else { j -= n3; if (j < n4) s = s4;
        else { j -= n4; s = s5; }}}}}
        float4 v = s[j];
        uint2 u; u.x = pack_h2(v.x, v.y); u.y = pack_h2(v.z, v.w);
        dst[i] = u;
    }
}

// ---------------- LN(s)*w+b -> half, width 512 ----------------
__global__ void __launch_bounds__(128) ln_affine512h(
    const float* __restrict__ x, const float* __restrict__ w,
    const float* __restrict__ b, __half* __restrict__ out)
{
    int row = blockIdx.x;
    const float4* xr = (const float4*)(x + (size_t)row * CND);
    float4 v = xr[threadIdx.x];
    float s  = v.x + v.y + v.z + v.w;
    float ss = v.x*v.x + v.y*v.y + v.z*v.z + v.w*v.w;
    s = warp_sum(s); ss = warp_sum(ss);
    __shared__ float sh[8];
    int wid = threadIdx.x >> 5, lid = threadIdx.x & 31;
    if (lid == 0) { sh[wid] = s; sh[4 + wid] = ss; }
    __syncthreads();
    s  = sh[0] + sh[1] + sh[2] + sh[3];
    ss = sh[4] + sh[5] + sh[6] + sh[7];
    float mean = s * (1.0f / CND);
    float var  = ss * (1.0f / CND) - mean * mean;
    float rinv = rsqrtf(var + EPSF);
    int d = threadIdx.x * 4;
    float4 wv = *(const float4*)(w + d);
    float4 bv = *(const float4*)(b + d);
    uint2 u;
    u.x = pack_h2((v.x - mean) * rinv * wv.x + bv.x, (v.y - mean) * rinv * wv.y + bv.y);
    u.y = pack_h2((v.z - mean) * rinv * wv.z + bv.z, (v.w - mean) * rinv * wv.w + bv.w);
    ((uint2*)(out + (size_t)row * CND))[threadIdx.x] = u;
}

// ---------------- LN(h)*(1+scale)+shift -> half, width 1024 ----------------
__global__ void __launch_bounds__(256) ln_mod1024h(
    const float* __restrict__ x, const float* __restrict__ mod,
    int scale_off, int shift_off, __half* __restrict__ out)
{
    int row = blockIdx.x;
    float4 v = ((const float4*)(x + (size_t)row * CD))[threadIdx.x];
    float s  = v.x + v.y + v.z + v.w;
    float ss = v.x*v.x + v.y*v.y + v.z*v.z + v.w*v.w;
    s = warp_sum(s); ss = warp_sum(ss);
    __shared__ float sh[16];
    int wid = threadIdx.x >> 5, lid = threadIdx.x & 31;
    if (lid == 0) { sh[wid] = s; sh[8 + wid] = ss; }
    __syncthreads();
    s = 0.f; ss = 0.f;
#pragma unroll
    for (int i = 0; i < 8; i++) { s += sh[i]; ss += sh[8 + i]; }
    float mean = s * (1.0f / CD);
    float var  = ss * (1.0f / CD) - mean * mean;
    float rinv = rsqrtf(var + EPSF);
    int d = threadIdx.x * 4;
    const float* mrow = mod + (size_t)row * MODW;
    float4 sc = *(const float4*)(mrow + scale_off + d);
    float4 sf = *(const float4*)(mrow + shift_off + d);
    uint2 u;
    u.x = pack_h2(((v.x - mean) * rinv) * (1.0f + sc.x) + sf.x,
                  ((v.y - mean) * rinv) * (1.0f + sc.y) + sf.y);
    u.y = pack_h2(((v.z - mean) * rinv) * (1.0f + sc.z) + sf.z,
                  ((v.w - mean) * rinv) * (1.0f + sc.w) + sf.w);
    ((uint2*)(out + (size_t)row * CD))[threadIdx.x] = u;
}

// ---------------- fp16 NT GEMM, cp.async 2-stage ----------------
// EPI 0: float C = acc + bias
// EPI 1: half  C = silu(acc + bias)
// EPI 2: float C = res + (acc + bias) * gate
// EPI 3: half  C = acc + bias
#define GEMM_SMEM_H (2 * 2 * 128 * 20 * 4)
template<int EPI>
__global__ void __launch_bounds__(256, 2) gemm_h(
    const __half* __restrict__ A, const __half* __restrict__ W,
    const float* __restrict__ bias, void* __restrict__ Cv,
    int M, int N, int K,
    const float* __restrict__ res, const float* __restrict__ gate, int gate_off)
{
    extern __shared__ uint32_t dynh[];
    uint32_t* As = dynh;
    uint32_t* Ws = dynh + 2 * 128 * 20;

    int bm = blockIdx.y * 128;
    int bn = blockIdx.x * 128;
    int tid  = threadIdx.x;
    int warp = tid >> 5, lane = tid & 31;
    int g = lane >> 2, t = lane & 3;
    int wm = (warp & 1) * 64;
    int wn = (warp >> 1) * 32;

    float acc[4][4][4];
#pragma unroll
    for (int i = 0; i < 4; i++)
#pragma unroll
        for (int j = 0; j < 4; j++)
#pragma unroll
            for (int q = 0; q < 4; q++) acc[i][j][q] = 0.f;

#pragma unroll
    for (int cc = 0; cc < 2; cc++) {
        int c = tid + cc * 256;
        int row = c >> 2, seg = c & 3;
        uint32_t da = (uint32_t)__cvta_generic_to_shared(&As[row * 20 + seg * 4]);
        CP_ASYNC16(da, A + (size_t)(bm + row) * K + seg * 8);
        uint32_t dw = (uint32_t)__cvta_generic_to_shared(&Ws[row * 20 + seg * 4]);
        CP_ASYNC16(dw, W + (size_t)(bn + row) * K + seg * 8);
    }
    CP_COMMIT();

    int nIter = K >> 5;
    for (int it = 0; it < nIter; ++it) {
        if (it + 1 < nIter) {
            int k0n = (it + 1) << 5;
            int stn = (it + 1) & 1;
            uint32_t* An = As + (size_t)stn * 128 * 20;
            uint32_t* Wn = Ws + (size_t)stn * 128 * 20;
#pragma unroll
            for (int cc = 0; cc < 2; cc++) {
                int c = tid + cc * 256;
                int row = c >> 2, seg = c & 3;
                uint32_t da = (uint32_t)__cvta_generic_to_shared(&An[row * 20 + seg * 4]);
                CP_ASYNC16(da, A + (size_t)(bm + row) * K + k0n + seg * 8);
                uint32_t dw = (uint32_t)__cvta_generic_to_shared(&Wn[row * 20 + seg * 4]);
                CP_ASYNC16(dw, W + (size_t)(bn + row) * K + k0n + seg * 8);
            }
            CP_COMMIT();
            CP_WAIT(1);
        } else {
            CP_WAIT(0);
        }
        __syncthreads();
        int st = it & 1;
        const uint32_t* Ab = As + (size_t)st * 128 * 20;
        const uint32_t* Wb = Ws + (size_t)st * 128 * 20;
#pragma unroll
        for (int ks = 0; ks < 2; ks++) {
            int kp = ks * 8;
            uint32_t af[4][4];
#pragma unroll
            for (int mt = 0; mt < 4; mt++) {
                int r0 = wm + mt * 16 + g;
                af[mt][0] = Ab[(size_t)r0 * 20 + kp + t];
                af[mt][1] = Ab[(size_t)(r0 + 8) * 20 + kp + t];
                af[mt][2] = Ab[(size_t)r0 * 20 + kp + t + 4];
                af[mt][3] = Ab[(size_t)(r0 + 8) * 20 + kp + t + 4];
            }
            uint32_t bf[4][2];
#pragma unroll
            for (int nt = 0; nt < 4; nt++) {
                int c0 = wn + nt * 8 + g;
                bf[nt][0] = Wb[(size_t)c0 * 20 + kp + t];
                bf[nt][1] = Wb[(size_t)c0 * 20 + kp + t + 4];
            }
#pragma unroll
            for (int mt = 0; mt < 4; mt++)
#pragma unroll
                for (int nt = 0; nt < 4; nt++)
                    mma_fp16(acc[mt][nt], af[mt], bf[nt]);
        }
        __syncthreads();
    }

#pragma unroll
    for (int mt = 0; mt < 4; mt++) {
#pragma unroll
        for (int half = 0; half < 2; half++) {
            int row = bm + wm + mt * 16 + g + half * 8;
            const float* rr = (EPI == 2) ? res + (size_t)row * N : nullptr;
            const float* gr = (EPI == 2) ? gate + (size_t)row * MODW + gate_off : nullptr;
#pragma unroll
            for (int nt = 0; nt < 4; nt++) {
                int col = bn + wn + nt * 8 + 2 * t;
                float v0 = acc[mt][nt][half * 2 + 0] + bias[col];
                float v1 = acc[mt][nt][half * 2 + 1] + bias[col + 1];
                if (EPI == 1) {
                    v0 = v0 / (1.0f + expf(-v0));
                    v1 = v1 / (1.0f + expf(-v1));
                }
                if (EPI == 1 || EPI == 3) {
                    __half* cr = (__half*)Cv + (size_t)row * N;
                    *(uint32_t*)(cr + col) = pack_h2(v0, v1);
                } else {
                    if (EPI == 2) {
                        v0 = rr[col]     + v0 * gr[col];
                        v1 = rr[col + 1] + v1 * gr[col + 1];
                    }
                    float* cr = (float*)Cv + (size_t)row * N;
                    float2 o2; o2.x = v0; o2.y = v1;
                    *(float2*)(cr + col) = o2;
                }
            }
        }
    }
}

// ---------------- edge bias (frozen since round 9) ----------------
__global__ void __launch_bounds__(128) edge_bias_mma(
    const float* __restrict__ p, const float* __restrict__ lnw, const float* __restrict__ lnb,
    const float* __restrict__ ew, const float* __restrict__ eb, __half* __restrict__ bias)
{
    __shared__ float rows[128][68];
    __shared__ float W2T[16][68];
    __shared__ float meanv[128], rinvv[128], c1s[16], c2s[16];
    int tid = threadIdx.x;
    size_t base = (size_t)blockIdx.x * 128;

#pragma unroll
    for (int r = 0; r < 16; r++) {
        int id  = tid + r * 128;
        int row = id >> 4;
        int c4  = (id & 15) * 4;
        *(float4*)&rows[row][c4] = *(const float4*)(p + (base + row) * 64 + c4);
    }
    for (int i = tid; i < 1024; i += 128) {
        int h = i >> 6, k = i & 63;
        W2T[h][k] = ew[i] * lnw[k];
    }
    if (tid < 16) {
        float a = 0.f, b2 = 0.f;
        for (int k = 0; k < 64; k++) {
            float e = ew[tid * 64 + k];
            a  += lnw[k] * e;
            b2 += lnb[k] * e;
        }
        c1s[tid] = a;
        c2s[tid] = b2 + eb[tid];
    }
    __syncthreads();

    {
        float s = 0.f, ss = 0.f;
#pragma unroll
        for (int q = 0; q < 16; q++) {
            float4 x = *(const float4*)&rows[tid][q * 4];
            s  += x.x + x.y + x.z + x.w;
            ss += x.x*x.x + x.y*x.y + x.z*x.z + x.w*x.w;
        }
        float mean = s * (1.0f / 64.0f);
        float var  = ss * (1.0f / 64.0f) - mean * mean;
        meanv[tid] = mean;
        rinvv[tid] = rsqrtf(var + EPSF);
    }
    __syncthreads();

    int warp = tid >> 5, lane = tid & 31;
    int g = lane >> 2, t = lane & 3;
    float acc[2][2][4];
#pragma unroll
    for (int i = 0; i < 2; i++)
#pragma unroll
        for (int j = 0; j < 2; j++)
#pragma unroll
            for (int q = 0; q < 4; q++) acc[i][j][q] = 0.f;

#pragma unroll
    for (int ks = 0; ks < 8; ks++) {
        int kk = ks * 8;
        uint32_t af[2][4];
#pragma unroll
        for (int mt = 0; mt < 2; mt++) {
            int r0 = warp * 32 + mt * 16 + g;
            af[mt][0] = __float_as_uint(rows[r0][kk + t]);
            af[mt][1] = __float_as_uint(rows[r0 + 8][kk + t]);
            af[mt][2] = __float_as_uint(rows[r0][kk + t + 4]);
            af[mt][3] = __float_as_uint(rows[r0 + 8][kk + t + 4]);
        }
        uint32_t bf[2][2];
#pragma unroll
        for (int nt = 0; nt < 2; nt++) {
            int c0 = nt * 8 + g;
            bf[nt][0] = __float_as_uint(W2T[c0][kk + t]);
            bf[nt][1] = __float_as_uint(W2T[c0][kk + t + 4]);
        }
#pragma unroll
        for (int mt = 0; mt < 2; mt++)
#pragma unroll
            for (int nt = 0; nt < 2; nt++)
                mma_tf32(acc[mt][nt], af[mt], bf[nt]);
    }

    int b  = (int)(base >> 18);
    int ij = (int)(base & 262143);
    int i  = ij >> 9;
    int j0 = ij & 511;
    __half* bb = bias + (((size_t)b * 16) * 512 + i) * 512 + j0;
#pragma unroll
    for (int mt = 0; mt < 2; mt++) {
#pragma unroll
        for (int half = 0; half < 2; half++) {
            int rl = warp * 32 + mt * 16 + g + half * 8;
            float m  = meanv[rl];
            float rv = rinvv[rl];
#pragma unroll
            for (int nt = 0; nt < 2; nt++) {
#pragma unroll
                for (int c = 0; c < 2; c++) {
                    int h = nt * 8 + 2 * t + c;
                    bb[(size_t)h * 512 * 512 + rl] =
                        __float2half(rv * (acc[mt][nt][half * 2 + c] - m * c1s[h]) + c2s[h]);
                }
            }
        }
    }
}

// ---------------- flash v2: all-fp16 MMA, register-resident P ----------------
// grid (4 i-tiles, 64 bh), 256 threads (8 warps x 16 rows).
// Static smem: Qh[128][36]w, Kh[64][36]w, Vt[64][36]w = 36 KB.
__global__ void __launch_bounds__(256) flash_h(
    const __half* __restrict__ bias, const __half* __restrict__ qkvh, __half* __restrict__ o)
{
    __shared__ uint32_t Qh[128 * 36];
    __shared__ uint32_t Kh[64 * 36];
    __shared__ uint32_t Vt[64 * 36];   // transposed: word [d][j-pair]

    int bh = blockIdx.y; int b = bh >> 4, h = bh & 15;
    int i0 = blockIdx.x * 128;
    int tid  = threadIdx.x;
    int warp = tid >> 5, lane = tid & 31;
    int g = lane >> 2, t = lane & 3;
    int r0 = warp * 16 + g;

    const __half* qb = qkvh + (size_t)(b * CL) * (3 * CD) + h * CDH;
    const __half* kb = qb + CD;
    const __half* vb = qb + 2 * CD;
    const __half* bbase = bias + ((size_t)bh * CL + i0) * CL;

    // Q tile: 128 rows x 8 chunks(16B)
#pragma unroll
    for (int r = 0; r < 4; r++) {
        int id  = tid + r * 256;
        int row = id >> 3, seg = id & 7;
        uint32_t dst = (uint32_t)__cvta_generic_to_shared(&Qh[row * 36 + seg * 4]);
        CP_ASYNC16(dst, qb + (size_t)(i0 + row) * (3 * CD) + seg * 8);
    }
    CP_COMMIT();

    float Oa[8][4];
#pragma unroll
    for (int nt = 0; nt < 8; nt++)
#pragma unroll
        for (int q = 0; q < 4; q++) Oa[nt][q] = 0.f;
    float m0 = -1e30f, m1 = -1e30f, l0 = 0.f, l1 = 0.f;

    for (int j0 = 0; j0 < CL; j0 += 64) {
        // K tile: cp.async, 64 rows x 8 chunks
#pragma unroll
        for (int r = 0; r < 2; r++) {
            int id  = tid + r * 256;
            int row = id >> 3, seg = id & 7;
            uint32_t dst = (uint32_t)__cvta_generic_to_shared(&Kh[row * 36 + seg * 4]);
            CP_ASYNC16(dst, kb + (size_t)(j0 + row) * (3 * CD) + seg * 8);
        }
        CP_COMMIT();
        // V tile transposed: thread (jw = tid>>4 (+16), dg = tid&15)
#pragma unroll
        for (int r = 0; r < 2; r++) {
            int jw = (tid >> 4) + r * 16;   // 0..31 (j pairs)
            int dg = tid & 15;              // d group of 4
            const __half* va = vb + (size_t)(j0 + 2 * jw) * (3 * CD) + dg * 4;
            uint2 ua = *(const uint2*)va;
            uint2 ub = *(const uint2*)(va + 3 * CD);
            Vt[(dg * 4 + 0) * 36 + jw] = (ua.x & 0xFFFFu)  | (ub.x << 16);
            Vt[(dg * 4 + 1) * 36 + jw] = (ua.x >> 16)      | (ub.x & 0xFFFF0000u);
            Vt[(dg * 4 + 2) * 36 + jw] = (ua.y & 0xFFFFu)  | (ub.y << 16);
            Vt[(dg * 4 + 3) * 36 + jw] = (ua.y >> 16)      | (ub.y & 0xFFFF0000u);
        }
        CP_WAIT(0);
        __syncthreads();

        // S = Q K^T (fp16 m16n8k16)
        float sa[8][4];
#pragma unroll
        for (int nt = 0; nt < 8; nt++)
#pragma unroll
            for (int q = 0; q < 4; q++) sa[nt][q] = 0.f;
#pragma unroll
        for (int ks = 0; ks < 4; ks++) {
            int kp = ks * 8;
            uint32_t af[4];
            af[0] = Qh[r0 * 36 + kp + t];
            af[1] = Qh[(r0 + 8) * 36 + kp + t];
            af[2] = Qh[r0 * 36 + kp + t + 4];
            af[3] = Qh[(r0 + 8) * 36 + kp + t + 4];
#pragma unroll
            for (int nt = 0; nt < 8; nt++) {
                int c0 = nt * 8 + g;
                uint32_t bf[2];
                bf[0] = Kh[c0 * 36 + kp + t];
                bf[1] = Kh[c0 * 36 + kp + t + 4];
                mma_fp16(sa[nt], af, bf);
            }
        }

        // finish S: *1/8 + bias(half); row maxima
        float mt0 = -1e30f, mt1 = -1e30f;
#pragma unroll
        for (int nt = 0; nt < 8; nt++) {
            int col = j0 + nt * 8 + 2 * t;
            float2 b0 = __half22float2(*(const __half2*)(bbase + (size_t)r0 * CL + col));
            float2 b1 = __half22float2(*(const __half2*)(bbase + (size_t)(r0 + 8) * CL + col));
            sa[nt][0] = fmaf(sa[nt][0], 0.125f, b0.x);
            sa[nt][1] = fmaf(sa[nt][1], 0.125f, b0.y);
            sa[nt][2] = fmaf(sa[nt][2], 0.125f, b1.x);
            sa[nt][3] = fmaf(sa[nt][3], 0.125f, b1.y);
            mt0 = fmaxf(mt0, fmaxf(sa[nt][0], sa[nt][1]));
            mt1 = fmaxf(mt1, fmaxf(sa[nt][2], sa[nt][3]));
        }
#pragma unroll
        for (int x = 1; x <= 2; x <<= 1) {
            mt0 = fmaxf(mt0, __shfl_xor_sync(0xffffffffu, mt0, x));
            mt1 = fmaxf(mt1, __shfl_xor_sync(0xffffffffu, mt1, x));
        }
        float mn0 = fmaxf(m0, mt0), mn1 = fmaxf(m1, mt1);
        float sc0 = expf(m0 - mn0), sc1 = expf(m1 - mn1);
        m0 = mn0; m1 = mn1;

        // P = exp(S - m) in registers; sums
        float ps0 = 0.f, ps1 = 0.f;
#pragma unroll
        for (int nt = 0; nt < 8; nt++) {
            sa[nt][0] = expf(sa[nt][0] - m0);
            sa[nt][1] = expf(sa[nt][1] - m0);
            sa[nt][2] = expf(sa[nt][2] - m1);
            sa[nt][3] = expf(sa[nt][3] - m1);
            ps0 += sa[nt][0] + sa[nt][1];
            ps1 += sa[nt][2] + sa[nt][3];
        }
#pragma unroll
        for (int x = 1; x <= 2; x <<= 1) {
            ps0 += __shfl_xor_sync(0xffffffffu, ps0, x);
            ps1 += __shfl_xor_sync(0xffffffffu, ps1, x);
        }
        l0 = l0 * sc0 + ps0;
        l1 = l1 * sc1 + ps1;
#pragma unroll
        for (int nt = 0; nt < 8; nt++) {
            Oa[nt][0] *= sc0; Oa[nt][1] *= sc0;
            Oa[nt][2] *= sc1; Oa[nt][3] *= sc1;
        }

        // O += P @ V: P packed from registers (S-accum layout == fp16 A-frag layout)
#pragma unroll
        for (int ks = 0; ks < 4; ks++) {
            uint32_t af[4];
            af[0] = pack_h2(sa[2*ks][0],     sa[2*ks][1]);
            af[1] = pack_h2(sa[2*ks][2],     sa[2*ks][3]);
            af[2] = pack_h2(sa[2*ks + 1][0], sa[2*ks + 1][1]);
            af[3] = pack_h2(sa[2*ks + 1][2], sa[2*ks + 1][3]);
#pragma unroll
            for (int nt = 0; nt < 8; nt++) {
                int c0 = nt * 8 + g;
                uint32_t bf[2];
                bf[0] = Vt[c0 * 36 + ks * 8 + t];
                bf[1] = Vt[c0 * 36 + ks * 8 + t + 4];
                mma_fp16(Oa[nt], af, bf);
            }
        }
        __syncthreads();   // done reading Kh/Vt before next iteration overwrites
    }

    float il0 = 1.0f / l0, il1 = 1.0f / l1;
    __half* o0 = o + (size_t)(b * CL + i0 + r0) * CD + h * CDH;
    __half* o1 = o + (size_t)(b * CL + i0 + r0 + 8) * CD + h * CDH;
#pragma unroll
    for (int nt = 0; nt < 8; nt++) {
        int d = nt * 8 + 2 * t;
        *(uint32_t*)(o0 + d) = pack_h2(Oa[nt][0] * il0, Oa[nt][1] * il0);
        *(uint32_t*)(o1 + d) = pack_h2(Oa[nt][2] * il1, Oa[nt][3] * il1);
    }
}

// ---------------- launch ----------------
extern "C" void kernel_launch(void* const* d_in, const int* in_sizes, int n_in,
                              void* d_out, int out_size)
{
    const float* h_in  = (const float*)d_in[0];
    const float* s_in  = (const float*)d_in[1];
    const float* p_in  = (const float*)d_in[2];
    const float* aln_w = (const float*)d_in[3];
    const float* aln_b = (const float*)d_in[4];
    const float* aw1   = (const float*)d_in[5];
    const float* ab1   = (const float*)d_in[6];
    const float* aw2   = (const float*)d_in[7];
    const float* ab2   = (const float*)d_in[8];
    const float* eln_w = (const float*)d_in[9];
    const float* eln_b = (const float*)d_in[10];
    const float* ew    = (const float*)d_in[11];
    const float* eb    = (const float*)d_in[12];
    const float* in_w  = (const float*)d_in[13];
    const float* in_b  = (const float*)d_in[14];
    const float* out_w = (const float*)d_in[15];
    const float* out_b = (const float*)d_in[16];
    const float* mw1   = (const float*)d_in[17];
    const float* mb1   = (const float*)d_in[18];
    const float* mw2   = (const float*)d_in[19];
    const float* mb2   = (const float*)d_in[20];
    float* out = (float*)d_out;

    float *mod, *h2;
    __half *sln_h, *t1_h, *x_h, *qkv_h, *o_h, *t2_h, *biasb, *wh;
    cudaGetSymbolAddress((void**)&sln_h, g_sln_h);
    cudaGetSymbolAddress((void**)&t1_h,  g_t1_h);
    cudaGetSymbolAddress((void**)&mod,   g_mod);
    cudaGetSymbolAddress((void**)&biasb, g_bias);
    cudaGetSymbolAddress((void**)&x_h,   g_x_h);
    cudaGetSymbolAddress((void**)&qkv_h, g_qkv_h);
    cudaGetSymbolAddress((void**)&o_h,   g_o_h);
    cudaGetSymbolAddress((void**)&h2,    g_h2);
    cudaGetSymbolAddress((void**)&t2_h,  g_t2_h);
    cudaGetSymbolAddress((void**)&wh,    g_wh);

    cudaFuncSetAttribute(gemm_h<0>, cudaFuncAttributeMaxDynamicSharedMemorySize, GEMM_SMEM_H);
    cudaFuncSetAttribute(gemm_h<1>, cudaFuncAttributeMaxDynamicSharedMemorySize, GEMM_SMEM_H);
    cudaFuncSetAttribute(gemm_h<2>, cudaFuncAttributeMaxDynamicSharedMemorySize, GEMM_SMEM_H);
    cudaFuncSetAttribute(gemm_h<3>, cudaFuncAttributeMaxDynamicSharedMemorySize, GEMM_SMEM_H);

    // all weight conversions in one kernel
    cvt_all<<<1024, 256>>>((const float4*)aw1, (const float4*)aw2, (const float4*)in_w,
                           (const float4*)out_w, (const float4*)mw1, (const float4*)mw2,
                           (uint2*)wh);

    // adaLN modulation chain
    ln_affine512h<<<NTOK, 128>>>(s_in, aln_w, aln_b, sln_h);
    gemm_h<1><<<dim3(CND / 128, NTOK / 128), 256, GEMM_SMEM_H>>>(sln_h, wh + OFF_AW1, ab1,
        t1_h, NTOK, CND, CND, nullptr, nullptr, 0);
    gemm_h<0><<<dim3(MODW / 128, NTOK / 128), 256, GEMM_SMEM_H>>>(t1_h, wh + OFF_AW2, ab2,
        mod, NTOK, MODW, CND, nullptr, nullptr, 0);

    // edge bias (fp16)
    edge_bias_mma<<<(CB * CL * CL) / 128, 128>>>(p_in, eln_w, eln_b, ew, eb, biasb);

    // attention branch
    ln_mod1024h<<<NTOK, 256>>>(h_in, mod, /*scale*/CD, /*shift*/0, x_h);
    gemm_h<3><<<dim3(3 * CD / 128, NTOK / 128), 256, GEMM_SMEM_H>>>(x_h, wh + OFF_INW, in_b,
        qkv_h, NTOK, 3 * CD, CD, nullptr, nullptr, 0);
    flash_h<<<dim3(CL / 128, CB * CH), 256>>>(biasb, qkv_h, o_h);
    gemm_h<2><<<dim3(CD / 128, NTOK / 128), 256, GEMM_SMEM_H>>>(o_h, wh + OFF_OUTW, out_b,
        h2, NTOK, CD, CD, h_in, mod, 2 * CD);

    // gated MLP branch
    ln_mod1024h<<<NTOK, 256>>>(h2, mod, /*scale*/4 * CD, /*shift*/3 * CD, x_h);
    gemm_h<1><<<dim3(CMLP / 128, NTOK / 128), 256, GEMM_SMEM_H>>>(x_h, wh + OFF_MW1, mb1,
        t2_h, NTOK, CMLP, CD, nullptr, nullptr, 0);
    gemm_h<2><<<dim3(CD / 128, NTOK / 128), 256, GEMM_SMEM_H>>>(t2_h, wh + OFF_MW2, mb2,
        out, NTOK, CD, CMLP, h2, mod, 5 * CD);
}